// round 2
// baseline (speedup 1.0000x reference)
#include <cuda_runtime.h>
#include <math.h>

// Problem constants
#define SEQ 2048
#define DM  1024
#define NH  16
#define DKH 64

// ---------------------------------------------------------------------------
// Scratch (device globals: allocation-free per harness rules)
// ---------------------------------------------------------------------------
__device__ float g_Q[SEQ * DM];
__device__ float g_K[SEQ * DM];
__device__ float g_V[SEQ * DM];
__device__ float g_CTX[SEQ * DM];
__device__ float g_OUT[SEQ * DM];                       // only used in odd out layouts
__device__ float g_ATTN[(size_t)NH * SEQ * SEQ];        // used when attn not in d_out

// ---------------------------------------------------------------------------
// SGEMM: C[M,N] = A[M,K] @ W[N,K]^T + bias[N]   (torch Linear convention)
// 128x128 tile, BK=8, 256 threads, 8x8 per-thread microtile.
// ---------------------------------------------------------------------------
__global__ __launch_bounds__(256) void sgemm_wt(const float* __restrict__ A,
                                                const float* __restrict__ W,
                                                const float* __restrict__ bias,
                                                float* __restrict__ C,
                                                int M, int N, int K)
{
    __shared__ float sA[8][128];
    __shared__ float sB[8][128];

    const int tid = threadIdx.x;
    const int bm  = blockIdx.y * 128;
    const int bn  = blockIdx.x * 128;
    const int tx  = tid & 15;   // 0..15 -> N direction
    const int ty  = tid >> 4;   // 0..15 -> M direction
    const int lr  = tid >> 1;        // 0..127 load row
    const int lc  = (tid & 1) << 2;  // 0 or 4 load col (float4)

    float acc[8][8];
#pragma unroll
    for (int i = 0; i < 8; ++i)
#pragma unroll
        for (int j = 0; j < 8; ++j) acc[i][j] = 0.f;

    const float* Aptr = A + (size_t)(bm + lr) * K + lc;
    const float* Wptr = W + (size_t)(bn + lr) * K + lc;

    for (int k0 = 0; k0 < K; k0 += 8) {
        float4 av = *(const float4*)(Aptr + k0);
        float4 wv = *(const float4*)(Wptr + k0);
        __syncthreads();
        sA[lc + 0][lr] = av.x; sA[lc + 1][lr] = av.y;
        sA[lc + 2][lr] = av.z; sA[lc + 3][lr] = av.w;
        sB[lc + 0][lr] = wv.x; sB[lc + 1][lr] = wv.y;
        sB[lc + 2][lr] = wv.z; sB[lc + 3][lr] = wv.w;
        __syncthreads();
#pragma unroll
        for (int kk = 0; kk < 8; ++kk) {
            float4 a0 = *(const float4*)&sA[kk][ty * 8];
            float4 a1 = *(const float4*)&sA[kk][ty * 8 + 4];
            float4 b0 = *(const float4*)&sB[kk][tx * 8];
            float4 b1 = *(const float4*)&sB[kk][tx * 8 + 4];
            float ra[8] = {a0.x, a0.y, a0.z, a0.w, a1.x, a1.y, a1.z, a1.w};
            float rb[8] = {b0.x, b0.y, b0.z, b0.w, b1.x, b1.y, b1.z, b1.w};
#pragma unroll
            for (int i = 0; i < 8; ++i)
#pragma unroll
                for (int j = 0; j < 8; ++j)
                    acc[i][j] += ra[i] * rb[j];
        }
    }

    float bset[8];
#pragma unroll
    for (int j = 0; j < 8; ++j) bset[j] = bias[bn + tx * 8 + j];

#pragma unroll
    for (int i = 0; i < 8; ++i) {
        float4 c0, c1;
        c0.x = acc[i][0] + bset[0]; c0.y = acc[i][1] + bset[1];
        c0.z = acc[i][2] + bset[2]; c0.w = acc[i][3] + bset[3];
        c1.x = acc[i][4] + bset[4]; c1.y = acc[i][5] + bset[5];
        c1.z = acc[i][6] + bset[6]; c1.w = acc[i][7] + bset[7];
        float* crow = &C[(size_t)(bm + ty * 8 + i) * N + bn + tx * 8];
        *(float4*)(crow)     = c0;
        *(float4*)(crow + 4) = c1;
    }
}

// ---------------------------------------------------------------------------
// Fused attention: per block = (one head, 16 query rows).
//   scores(16x2048) in dynamic smem -> softmax in-place -> write attn ->
//   ctx(16x64) = P @ V_h  (V tiles reuse the K-tile smem buffer)
// smem: sQ 16x68 | sK 128x68 | sS 16x2048  = 170,240 B dynamic
// ---------------------------------------------------------------------------
#define AROWS 16
#define AKT   128
#define KPAD  68
#define ATTN_SMEM ((AROWS * KPAD + AKT * KPAD + AROWS * SEQ) * 4)

__global__ __launch_bounds__(256) void attn_kernel(const float* __restrict__ Q,
                                                   const float* __restrict__ K,
                                                   const float* __restrict__ V,
                                                   const int* __restrict__ mask,
                                                   float* __restrict__ attn_out,
                                                   float* __restrict__ ctx)
{
    extern __shared__ float sm[];
    float* sQ = sm;                              // AROWS x KPAD
    float* sK = sm + AROWS * KPAD;               // AKT x KPAD (reused for V)
    float* sS = sm + AROWS * KPAD + AKT * KPAD;  // AROWS x SEQ

    const int h    = blockIdx.y;
    const int row0 = blockIdx.x * AROWS;
    const int tid  = threadIdx.x;

    // Load Q tile: 16 rows x 64 dims (256 float4s, one per thread)
    {
        int r = tid >> 4;
        int c = tid & 15;
        float4 qv = *(const float4*)&Q[(size_t)(row0 + r) * DM + h * DKH + c * 4];
        *(float4*)&sQ[r * KPAD + c * 4] = qv;
    }
    __syncthreads();

    const int rg = tid & 7;    // rows 2*rg, 2*rg+1
    const int kg = tid >> 3;   // keys kg + 32*i, i in 0..3

    // ---- scores ----
    for (int t = 0; t < SEQ / AKT; ++t) {
        __syncthreads();   // sK reuse guard
#pragma unroll
        for (int i = 0; i < 8; ++i) {
            int idx = tid + i * 256;
            int j = idx >> 4, c = idx & 15;
            *(float4*)&sK[j * KPAD + c * 4] =
                *(const float4*)&K[(size_t)(t * AKT + j) * DM + h * DKH + c * 4];
        }
        __syncthreads();

        float acc0[4] = {0.f, 0.f, 0.f, 0.f};
        float acc1[4] = {0.f, 0.f, 0.f, 0.f};
        const float* q0 = &sQ[(2 * rg) * KPAD];
        const float* q1 = &sQ[(2 * rg + 1) * KPAD];
#pragma unroll
        for (int d = 0; d < DKH; d += 4) {
            float4 qa = *(const float4*)&q0[d];
            float4 qb = *(const float4*)&q1[d];
#pragma unroll
            for (int i = 0; i < 4; ++i) {
                float4 kv = *(const float4*)&sK[(kg + 32 * i) * KPAD + d];
                acc0[i] += qa.x * kv.x + qa.y * kv.y + qa.z * kv.z + qa.w * kv.w;
                acc1[i] += qb.x * kv.x + qb.y * kv.y + qb.z * kv.z + qb.w * kv.w;
            }
        }
#pragma unroll
        for (int i = 0; i < 4; ++i) {
            int j = t * AKT + kg + 32 * i;
            bool keep = (mask[j] != 0);
            sS[(2 * rg) * SEQ + j]     = keep ? acc0[i] * 0.125f : -1e9f;
            sS[(2 * rg + 1) * SEQ + j] = keep ? acc1[i] * 0.125f : -1e9f;
        }
    }
    __syncthreads();

    // ---- softmax (8 warps x 2 rows), write attn_weights ----
    {
        int warp = tid >> 5, lane = tid & 31;
        for (int r = warp * 2; r < warp * 2 + 2; ++r) {
            float* row = &sS[r * SEQ];
            float m = -INFINITY;
            for (int j = lane; j < SEQ; j += 32) m = fmaxf(m, row[j]);
#pragma unroll
            for (int o = 16; o; o >>= 1) m = fmaxf(m, __shfl_xor_sync(0xffffffffu, m, o));
            float sum = 0.f;
            for (int j = lane; j < SEQ; j += 32) {
                float e = __expf(row[j] - m);
                row[j] = e;
                sum += e;
            }
#pragma unroll
            for (int o = 16; o; o >>= 1) sum += __shfl_xor_sync(0xffffffffu, sum, o);
            float inv = 1.0f / sum;
            float* gattn = &attn_out[((size_t)h * SEQ + (row0 + r)) * SEQ];
            for (int j = lane * 4; j < SEQ; j += 128) {
                float4 p = *(float4*)&row[j];
                p.x *= inv; p.y *= inv; p.z *= inv; p.w *= inv;
                *(float4*)&row[j]   = p;
                *(float4*)&gattn[j] = p;
            }
        }
    }
    __syncthreads();

    // ---- ctx = P @ V_h ----
    {
        int r  = tid >> 4;   // 0..15
        int dg = tid & 15;   // d = dg*4
        float4 accv = {0.f, 0.f, 0.f, 0.f};
        for (int t = 0; t < SEQ / AKT; ++t) {
            __syncthreads();   // sK(V) reuse guard
#pragma unroll
            for (int i = 0; i < 8; ++i) {
                int idx = tid + i * 256;
                int j = idx >> 4, c = idx & 15;
                *(float4*)&sK[j * KPAD + c * 4] =
                    *(const float4*)&V[(size_t)(t * AKT + j) * DM + h * DKH + c * 4];
            }
            __syncthreads();
            const float* prow = &sS[r * SEQ + t * AKT];
#pragma unroll 4
            for (int j = 0; j < AKT; ++j) {
                float p = prow[j];
                float4 v = *(const float4*)&sK[j * KPAD + dg * 4];
                accv.x += p * v.x; accv.y += p * v.y;
                accv.z += p * v.z; accv.w += p * v.w;
            }
        }
        *(float4*)&ctx[(size_t)(row0 + r) * DM + h * DKH + dg * 4] = accv;
    }
}

// ---------------------------------------------------------------------------
extern "C" void kernel_launch(void* const* d_in, const int* in_sizes, int n_in,
                              void* d_out, int out_size)
{
    const float* q    = (const float*)d_in[0];
    const float* k    = (const float*)d_in[1];
    const float* v    = (const float*)d_in[2];
    const int*   mask = (const int*)  d_in[3];
    const float* Wq   = (const float*)d_in[4];
    const float* bq   = (const float*)d_in[5];
    const float* Wk   = (const float*)d_in[6];
    const float* bk   = (const float*)d_in[7];
    const float* Wv   = (const float*)d_in[8];
    const float* bv   = (const float*)d_in[9];
    const float* Wo   = (const float*)d_in[10];
    const float* bo   = (const float*)d_in[11];

    float *Qp, *Kp, *Vp, *Cp, *Ap, *Op;
    cudaGetSymbolAddress((void**)&Qp, g_Q);
    cudaGetSymbolAddress((void**)&Kp, g_K);
    cudaGetSymbolAddress((void**)&Vp, g_V);
    cudaGetSymbolAddress((void**)&Cp, g_CTX);
    cudaGetSymbolAddress((void**)&Ap, g_ATTN);
    cudaGetSymbolAddress((void**)&Op, g_OUT);

    const size_t OUT_ELEMS  = (size_t)SEQ * DM;              // 2,097,152
    const size_t ATTN_ELEMS = (size_t)NH * SEQ * SEQ;        // 67,108,864

    float* outp = (float*)d_out;
    float* attnp;
    if ((size_t)out_size >= OUT_ELEMS + ATTN_ELEMS) {
        attnp = outp + OUT_ELEMS;          // tuple (out, attn) concatenated
    } else if ((size_t)out_size == ATTN_ELEMS) {
        attnp = (float*)d_out;             // only attn expected
        outp  = Op;
    } else {
        attnp = Ap;                        // only out expected
    }

    cudaFuncSetAttribute(attn_kernel,
                         cudaFuncAttributeMaxDynamicSharedMemorySize, ATTN_SMEM);

    dim3 pg(DM / 128, SEQ / 128);
    sgemm_wt<<<pg, 256>>>(q, Wq, bq, Qp, SEQ, DM, DM);
    sgemm_wt<<<pg, 256>>>(k, Wk, bk, Kp, SEQ, DM, DM);
    sgemm_wt<<<pg, 256>>>(v, Wv, bv, Vp, SEQ, DM, DM);

    attn_kernel<<<dim3(SEQ / AROWS, NH), 256, ATTN_SMEM>>>(Qp, Kp, Vp, mask, attnp, Cp);

    sgemm_wt<<<pg, 256>>>(Cp, Wo, bo, outp, SEQ, DM, DM);
}

// round 4
// speedup vs baseline: 1.3224x; 1.3224x over previous
#include <cuda_runtime.h>
#include <cuda_bf16.h>
#include <math.h>
#include <stdint.h>

// Problem constants
#define SEQ 2048
#define DM  1024
#define NH  16
#define DKH 64

// ===========================================================================
// Portable PTX helpers (base compute_103 target: NO tcgen05 anywhere)
// ===========================================================================
__device__ __forceinline__ uint32_t smem_to_u32(const void* smem_ptr) {
    uint32_t addr;
    asm("{ .reg .u64 tmp; cvta.to.shared.u64 tmp, %1; cvt.u32.u64 %0, tmp; }"
        : "=r"(addr) : "l"(smem_ptr));
    return addr;
}

#define LDSM_X4(r0, r1, r2, r3, addr) \
    asm volatile("ldmatrix.sync.aligned.m8n8.x4.shared.b16 {%0,%1,%2,%3}, [%4];" \
        : "=r"(r0), "=r"(r1), "=r"(r2), "=r"(r3) : "r"(addr))

#define MMA16816(c, a, b0, b1) \
    asm volatile("mma.sync.aligned.m16n8k16.row.col.f32.bf16.bf16.f32 " \
        "{%0,%1,%2,%3},{%4,%5,%6,%7},{%8,%9},{%0,%1,%2,%3};" \
        : "+f"((c)[0]), "+f"((c)[1]), "+f"((c)[2]), "+f"((c)[3]) \
        : "r"((a)[0]), "r"((a)[1]), "r"((a)[2]), "r"((a)[3]), "r"(b0), "r"(b1))

#define CP_ASYNC16(smaddr, gptr) \
    asm volatile("cp.async.cg.shared.global [%0], [%1], 16;" \
        :: "r"(smaddr), "l"(gptr))
#define CP_COMMIT() asm volatile("cp.async.commit_group;" ::: "memory")
#define CP_WAIT0()  asm volatile("cp.async.wait_group 0;" ::: "memory")
#define CP_WAIT1()  asm volatile("cp.async.wait_group 1;" ::: "memory")

// ===========================================================================
// Scratch (device globals: allocation-free per harness rules)
// ===========================================================================
__device__ float g_Q[SEQ * DM];
__device__ float g_K[SEQ * DM];
__device__ float g_V[SEQ * DM];
__device__ float g_CTX[SEQ * DM];
__device__ float g_OUT[SEQ * DM];
__device__ float g_ATTN[(size_t)NH * SEQ * SEQ];

// bf16 hi/lo split scratch
__device__ __nv_bfloat16 g_qh[SEQ * DM],  g_ql[SEQ * DM];
__device__ __nv_bfloat16 g_kh[SEQ * DM],  g_kl[SEQ * DM];
__device__ __nv_bfloat16 g_vh[SEQ * DM],  g_vl[SEQ * DM];
__device__ __nv_bfloat16 g_ch[SEQ * DM],  g_cl[SEQ * DM];
__device__ __nv_bfloat16 g_Wqh[DM * DM], g_Wql[DM * DM];
__device__ __nv_bfloat16 g_Wkh[DM * DM], g_Wkl[DM * DM];
__device__ __nv_bfloat16 g_Wvh[DM * DM], g_Wvl[DM * DM];
__device__ __nv_bfloat16 g_Woh[DM * DM], g_Wol[DM * DM];

// ===========================================================================
// Split-precision prep: x -> (bf16 hi, bf16 lo)
// ===========================================================================
struct PrepBatch {
    const float* src[8];
    __nv_bfloat16* hi[8];
    __nv_bfloat16* lo[8];
    int n4[8];
};

__global__ __launch_bounds__(256) void split_prep(PrepBatch pb)
{
    int z = blockIdx.z;
    int i = blockIdx.x * 256 + threadIdx.x;
    if (i >= pb.n4[z]) return;
    float4 v = ((const float4*)pb.src[z])[i];
    __nv_bfloat16 h0 = __float2bfloat16(v.x);
    __nv_bfloat16 h1 = __float2bfloat16(v.y);
    __nv_bfloat16 h2 = __float2bfloat16(v.z);
    __nv_bfloat16 h3 = __float2bfloat16(v.w);
    __nv_bfloat16 l0 = __float2bfloat16(v.x - __bfloat162float(h0));
    __nv_bfloat16 l1 = __float2bfloat16(v.y - __bfloat162float(h1));
    __nv_bfloat16 l2 = __float2bfloat16(v.z - __bfloat162float(h2));
    __nv_bfloat16 l3 = __float2bfloat16(v.w - __bfloat162float(h3));
    __nv_bfloat162* hp = (__nv_bfloat162*)pb.hi[z];
    __nv_bfloat162* lp = (__nv_bfloat162*)pb.lo[z];
    hp[2 * i]     = __nv_bfloat162(h0, h1);
    hp[2 * i + 1] = __nv_bfloat162(h2, h3);
    lp[2 * i]     = __nv_bfloat162(l0, l1);
    lp[2 * i + 1] = __nv_bfloat162(l2, l3);
}

// ===========================================================================
// mma.sync split-bf16 GEMM: C[M,N] = A[M,K] @ W[N,K]^T + bias[N]
// 128x128 block, BK=32, 256 threads (8 warps, 4x2), warp tile 32x64.
// cp.async double-buffered smem, pitch 40 bf16 (80B) => ldmatrix conflict-free.
// ===========================================================================
#define GP 40                      // smem pitch in bf16 elems (80 bytes)
#define TILE_B (128 * GP * 2)      // 10240 bytes per 128x32 tile
#define STAGE_B (4 * TILE_B)       // Ah, Al, Bh, Bl
#define GEMM_SMEM (2 * STAGE_B)    // 81920 bytes

struct GemmPtrs {
    const __nv_bfloat16 *Ah, *Al, *Bh, *Bl;
    const float* bias;
    float* C;
};
struct GemmBatch { GemmPtrs g[3]; };

__global__ __launch_bounds__(256) void gemm_mma(GemmBatch batch)
{
    GemmPtrs gp = batch.g[blockIdx.z];
    extern __shared__ char smem[];
    uint32_t sb = smem_to_u32(smem);

    const int tid  = threadIdx.x;
    const int lane = tid & 31;
    const int wid  = tid >> 5;
    const int wm   = wid >> 1;      // 0..3 : 32-row slab
    const int wn   = wid & 1;       // 0..1 : 64-col slab
    const int bm   = blockIdx.y * 128;
    const int bn   = blockIdx.x * 128;

    const __nv_bfloat16* tp[4] = { gp.Ah, gp.Al, gp.Bh, gp.Bl };

    float acc[2][8][4];
#pragma unroll
    for (int i = 0; i < 2; ++i)
#pragma unroll
        for (int j = 0; j < 8; ++j)
#pragma unroll
            for (int c = 0; c < 4; ++c) acc[i][j][c] = 0.f;

    // ---- async stage loader: 2048 16B-chunks, 8 per thread ----
    auto issue_stage = [&](int it, int s) {
#pragma unroll
        for (int j = 0; j < 8; ++j) {
            int c2  = tid + j * 256;
            int tt  = c2 >> 9;        // tile 0..3
            int idx = c2 & 511;
            int r   = idx >> 2;       // row 0..127
            int c   = idx & 3;        // 16B chunk in row
            uint32_t sm = sb + (uint32_t)(s * STAGE_B + tt * TILE_B + r * 80 + c * 16);
            int grow = ((tt < 2) ? bm : bn) + r;
            const __nv_bfloat16* g8 = tp[tt] + (size_t)grow * DM + it * 32 + c * 8;
            CP_ASYNC16(sm, g8);
        }
        CP_COMMIT();
    };

    issue_stage(0, 0);

    for (int it = 0; it < DM / 32; ++it) {
        const int s = it & 1;
        if (it + 1 < DM / 32) { issue_stage(it + 1, (it + 1) & 1); CP_WAIT1(); }
        else                  { CP_WAIT0(); }
        __syncthreads();

        const uint32_t base = sb + s * STAGE_B;
        const uint32_t aH = base;
        const uint32_t aL = base + TILE_B;
        const uint32_t bH = base + 2 * TILE_B;
        const uint32_t bL = base + 3 * TILE_B;

#pragma unroll
        for (int ks = 0; ks < 2; ++ks) {
            const uint32_t aoff = (uint32_t)((wm * 32 + (lane & 15)) * 80 + ks * 32 + (lane >> 4) * 16);
            uint32_t ah0[4], ah1[4], al0[4], al1[4];
            LDSM_X4(ah0[0], ah0[1], ah0[2], ah0[3], aH + aoff);
            LDSM_X4(ah1[0], ah1[1], ah1[2], ah1[3], aH + aoff + 16 * 80);
            LDSM_X4(al0[0], al0[1], al0[2], al0[3], aL + aoff);
            LDSM_X4(al1[0], al1[1], al1[2], al1[3], aL + aoff + 16 * 80);

            const int brow = (lane & 7) + ((lane >> 4) << 3);
            const uint32_t bko = (uint32_t)(ks * 32 + ((lane >> 3) & 1) * 16);
            uint32_t bh[4][4], bl[4][4];
#pragma unroll
            for (int p = 0; p < 4; ++p) {
                uint32_t boff = (uint32_t)((wn * 64 + p * 16 + brow) * 80) + bko;
                LDSM_X4(bh[p][0], bh[p][1], bh[p][2], bh[p][3], bH + boff);
                LDSM_X4(bl[p][0], bl[p][1], bl[p][2], bl[p][3], bL + boff);
            }

#pragma unroll
            for (int mf = 0; mf < 2; ++mf) {
                const uint32_t* Ah_ = mf ? ah1 : ah0;
                const uint32_t* Al_ = mf ? al1 : al0;
#pragma unroll
                for (int p = 0; p < 4; ++p) {
                    MMA16816(acc[mf][2 * p],     Ah_, bh[p][0], bh[p][1]);
                    MMA16816(acc[mf][2 * p + 1], Ah_, bh[p][2], bh[p][3]);
                    MMA16816(acc[mf][2 * p],     Ah_, bl[p][0], bl[p][1]);
                    MMA16816(acc[mf][2 * p + 1], Ah_, bl[p][2], bl[p][3]);
                    MMA16816(acc[mf][2 * p],     Al_, bh[p][0], bh[p][1]);
                    MMA16816(acc[mf][2 * p + 1], Al_, bh[p][2], bh[p][3]);
                }
            }
        }
        __syncthreads();
    }

    // ---- epilogue: add bias, store fp32 ----
    const int l4 = lane >> 2;
    const int l2 = (lane & 3) * 2;
#pragma unroll
    for (int mf = 0; mf < 2; ++mf) {
        int r0 = bm + wm * 32 + mf * 16 + l4;
#pragma unroll
        for (int nf = 0; nf < 8; ++nf) {
            int col = bn + wn * 64 + nf * 8 + l2;
            float2 bb = *(const float2*)&gp.bias[col];
            float2 v0 = { acc[mf][nf][0] + bb.x, acc[mf][nf][1] + bb.y };
            float2 v1 = { acc[mf][nf][2] + bb.x, acc[mf][nf][3] + bb.y };
            *(float2*)&gp.C[(size_t)r0 * DM + col]       = v0;
            *(float2*)&gp.C[(size_t)(r0 + 8) * DM + col] = v1;
        }
    }
}

// ===========================================================================
// Fused attention (unchanged, known-good fp32 path)
// ===========================================================================
#define AROWS 16
#define AKT   128
#define KPAD  68
#define ATTN_SMEM ((AROWS * KPAD + AKT * KPAD + AROWS * SEQ) * 4)

__global__ __launch_bounds__(256) void attn_kernel(const float* __restrict__ Q,
                                                   const float* __restrict__ K,
                                                   const float* __restrict__ V,
                                                   const int* __restrict__ mask,
                                                   float* __restrict__ attn_out,
                                                   float* __restrict__ ctx)
{
    extern __shared__ float sm[];
    float* sQ = sm;
    float* sK = sm + AROWS * KPAD;
    float* sS = sm + AROWS * KPAD + AKT * KPAD;

    const int h    = blockIdx.y;
    const int row0 = blockIdx.x * AROWS;
    const int tid  = threadIdx.x;

    {
        int r = tid >> 4;
        int c = tid & 15;
        float4 qv = *(const float4*)&Q[(size_t)(row0 + r) * DM + h * DKH + c * 4];
        *(float4*)&sQ[r * KPAD + c * 4] = qv;
    }
    __syncthreads();

    const int rg = tid & 7;
    const int kg = tid >> 3;

    for (int t = 0; t < SEQ / AKT; ++t) {
        __syncthreads();
#pragma unroll
        for (int i = 0; i < 8; ++i) {
            int idx = tid + i * 256;
            int j = idx >> 4, c = idx & 15;
            *(float4*)&sK[j * KPAD + c * 4] =
                *(const float4*)&K[(size_t)(t * AKT + j) * DM + h * DKH + c * 4];
        }
        __syncthreads();

        float acc0[4] = {0.f, 0.f, 0.f, 0.f};
        float acc1[4] = {0.f, 0.f, 0.f, 0.f};
        const float* q0 = &sQ[(2 * rg) * KPAD];
        const float* q1 = &sQ[(2 * rg + 1) * KPAD];
#pragma unroll
        for (int d = 0; d < DKH; d += 4) {
            float4 qa = *(const float4*)&q0[d];
            float4 qb = *(const float4*)&q1[d];
#pragma unroll
            for (int i = 0; i < 4; ++i) {
                float4 kv = *(const float4*)&sK[(kg + 32 * i) * KPAD + d];
                acc0[i] += qa.x * kv.x + qa.y * kv.y + qa.z * kv.z + qa.w * kv.w;
                acc1[i] += qb.x * kv.x + qb.y * kv.y + qb.z * kv.z + qb.w * kv.w;
            }
        }
#pragma unroll
        for (int i = 0; i < 4; ++i) {
            int j = t * AKT + kg + 32 * i;
            bool keep = (mask[j] != 0);
            sS[(2 * rg) * SEQ + j]     = keep ? acc0[i] * 0.125f : -1e9f;
            sS[(2 * rg + 1) * SEQ + j] = keep ? acc1[i] * 0.125f : -1e9f;
        }
    }
    __syncthreads();

    {
        int warp = tid >> 5, lane = tid & 31;
        for (int r = warp * 2; r < warp * 2 + 2; ++r) {
            float* row = &sS[r * SEQ];
            float m = -INFINITY;
            for (int j = lane; j < SEQ; j += 32) m = fmaxf(m, row[j]);
#pragma unroll
            for (int o = 16; o; o >>= 1) m = fmaxf(m, __shfl_xor_sync(0xffffffffu, m, o));
            float sum = 0.f;
            for (int j = lane; j < SEQ; j += 32) {
                float e = __expf(row[j] - m);
                row[j] = e;
                sum += e;
            }
#pragma unroll
            for (int o = 16; o; o >>= 1) sum += __shfl_xor_sync(0xffffffffu, sum, o);
            float inv = 1.0f / sum;
            float* gattn = &attn_out[((size_t)h * SEQ + (row0 + r)) * SEQ];
            for (int j = lane * 4; j < SEQ; j += 128) {
                float4 p = *(float4*)&row[j];
                p.x *= inv; p.y *= inv; p.z *= inv; p.w *= inv;
                *(float4*)&row[j]   = p;
                *(float4*)&gattn[j] = p;
            }
        }
    }
    __syncthreads();

    {
        int r  = tid >> 4;
        int dg = tid & 15;
        float4 accv = {0.f, 0.f, 0.f, 0.f};
        for (int t = 0; t < SEQ / AKT; ++t) {
            __syncthreads();
#pragma unroll
            for (int i = 0; i < 8; ++i) {
                int idx = tid + i * 256;
                int j = idx >> 4, c = idx & 15;
                *(float4*)&sK[j * KPAD + c * 4] =
                    *(const float4*)&V[(size_t)(t * AKT + j) * DM + h * DKH + c * 4];
            }
            __syncthreads();
            const float* prow = &sS[r * SEQ + t * AKT];
#pragma unroll 4
            for (int j = 0; j < AKT; ++j) {
                float p = prow[j];
                float4 v = *(const float4*)&sK[j * KPAD + dg * 4];
                accv.x += p * v.x; accv.y += p * v.y;
                accv.z += p * v.z; accv.w += p * v.w;
            }
        }
        *(float4*)&ctx[(size_t)(row0 + r) * DM + h * DKH + dg * 4] = accv;
    }
}

// ===========================================================================
extern "C" void kernel_launch(void* const* d_in, const int* in_sizes, int n_in,
                              void* d_out, int out_size)
{
    const float* q    = (const float*)d_in[0];
    const float* k    = (const float*)d_in[1];
    const float* v    = (const float*)d_in[2];
    const int*   mask = (const int*)  d_in[3];
    const float* Wq   = (const float*)d_in[4];
    const float* bq   = (const float*)d_in[5];
    const float* Wk   = (const float*)d_in[6];
    const float* bk   = (const float*)d_in[7];
    const float* Wv   = (const float*)d_in[8];
    const float* bv   = (const float*)d_in[9];
    const float* Wo   = (const float*)d_in[10];
    const float* bo   = (const float*)d_in[11];

    float *Qp, *Kp, *Vp, *Cp, *Ap, *Op;
    cudaGetSymbolAddress((void**)&Qp, g_Q);
    cudaGetSymbolAddress((void**)&Kp, g_K);
    cudaGetSymbolAddress((void**)&Vp, g_V);
    cudaGetSymbolAddress((void**)&Cp, g_CTX);
    cudaGetSymbolAddress((void**)&Ap, g_ATTN);
    cudaGetSymbolAddress((void**)&Op, g_OUT);

    __nv_bfloat16 *qh, *ql, *kh, *kl, *vh, *vl, *ch, *cl;
    __nv_bfloat16 *Wqh, *Wql, *Wkh, *Wkl, *Wvh, *Wvl, *Woh, *Wol;
    cudaGetSymbolAddress((void**)&qh, g_qh);   cudaGetSymbolAddress((void**)&ql, g_ql);
    cudaGetSymbolAddress((void**)&kh, g_kh);   cudaGetSymbolAddress((void**)&kl, g_kl);
    cudaGetSymbolAddress((void**)&vh, g_vh);   cudaGetSymbolAddress((void**)&vl, g_vl);
    cudaGetSymbolAddress((void**)&ch, g_ch);   cudaGetSymbolAddress((void**)&cl, g_cl);
    cudaGetSymbolAddress((void**)&Wqh, g_Wqh); cudaGetSymbolAddress((void**)&Wql, g_Wql);
    cudaGetSymbolAddress((void**)&Wkh, g_Wkh); cudaGetSymbolAddress((void**)&Wkl, g_Wkl);
    cudaGetSymbolAddress((void**)&Wvh, g_Wvh); cudaGetSymbolAddress((void**)&Wvl, g_Wvl);
    cudaGetSymbolAddress((void**)&Woh, g_Woh); cudaGetSymbolAddress((void**)&Wol, g_Wol);

    const size_t OUT_ELEMS  = (size_t)SEQ * DM;
    const size_t ATTN_ELEMS = (size_t)NH * SEQ * SEQ;

    float* outp = (float*)d_out;
    float* attnp;
    if ((size_t)out_size >= OUT_ELEMS + ATTN_ELEMS) {
        attnp = outp + OUT_ELEMS;
    } else if ((size_t)out_size == ATTN_ELEMS) {
        attnp = (float*)d_out;
        outp  = Op;
    } else {
        attnp = Ap;
    }

    cudaFuncSetAttribute(attn_kernel,
                         cudaFuncAttributeMaxDynamicSharedMemorySize, ATTN_SMEM);
    cudaFuncSetAttribute(gemm_mma,
                         cudaFuncAttributeMaxDynamicSharedMemorySize, GEMM_SMEM);

    // 1) split-precision prep
    {
        PrepBatch pb;
        pb.src[0] = q;  pb.hi[0] = qh;  pb.lo[0] = ql;  pb.n4[0] = SEQ * DM / 4;
        pb.src[1] = k;  pb.hi[1] = kh;  pb.lo[1] = kl;  pb.n4[1] = SEQ * DM / 4;
        pb.src[2] = v;  pb.hi[2] = vh;  pb.lo[2] = vl;  pb.n4[2] = SEQ * DM / 4;
        pb.src[3] = Wq; pb.hi[3] = Wqh; pb.lo[3] = Wql; pb.n4[3] = DM * DM / 4;
        pb.src[4] = Wk; pb.hi[4] = Wkh; pb.lo[4] = Wkl; pb.n4[4] = DM * DM / 4;
        pb.src[5] = Wv; pb.hi[5] = Wvh; pb.lo[5] = Wvl; pb.n4[5] = DM * DM / 4;
        pb.src[6] = Wo; pb.hi[6] = Woh; pb.lo[6] = Wol; pb.n4[6] = DM * DM / 4;
        pb.src[7] = q;  pb.hi[7] = qh;  pb.lo[7] = ql;  pb.n4[7] = 0;
        dim3 pg((SEQ * DM / 4 + 255) / 256, 1, 7);
        split_prep<<<pg, 256>>>(pb);
    }

    // 2) Q/K/V projections (batched, z = matrix)
    {
        GemmBatch gb;
        gb.g[0] = { qh, ql, Wqh, Wql, bq, Qp };
        gb.g[1] = { kh, kl, Wkh, Wkl, bk, Kp };
        gb.g[2] = { vh, vl, Wvh, Wvl, bv, Vp };
        gemm_mma<<<dim3(DM / 128, SEQ / 128, 3), 256, GEMM_SMEM>>>(gb);
    }

    // 3) fused attention (fp32)
    attn_kernel<<<dim3(SEQ / AROWS, NH), 256, ATTN_SMEM>>>(Qp, Kp, Vp, mask, attnp, Cp);

    // 4) split ctx, 5) output projection
    {
        PrepBatch pb;
        pb.src[0] = Cp; pb.hi[0] = ch; pb.lo[0] = cl; pb.n4[0] = SEQ * DM / 4;
        for (int i = 1; i < 8; ++i) { pb.src[i] = Cp; pb.hi[i] = ch; pb.lo[i] = cl; pb.n4[i] = 0; }
        dim3 pg((SEQ * DM / 4 + 255) / 256, 1, 1);
        split_prep<<<pg, 256>>>(pb);

        GemmBatch gb;
        gb.g[0] = { ch, cl, Woh, Wol, bo, outp };
        gb.g[1] = gb.g[0];
        gb.g[2] = gb.g[0];
        gemm_mma<<<dim3(DM / 128, SEQ / 128, 1), 256, GEMM_SMEM>>>(gb);
    }
}

// round 5
// speedup vs baseline: 3.0685x; 2.3205x over previous
#include <cuda_runtime.h>
#include <cuda_bf16.h>
#include <math.h>
#include <stdint.h>

// Problem constants
#define SEQ 2048
#define DM  1024
#define NH  16
#define DKH 64

// ===========================================================================
// Portable PTX helpers (base compute_103 target: NO tcgen05 anywhere)
// ===========================================================================
__device__ __forceinline__ uint32_t smem_to_u32(const void* smem_ptr) {
    uint32_t addr;
    asm("{ .reg .u64 tmp; cvta.to.shared.u64 tmp, %1; cvt.u32.u64 %0, tmp; }"
        : "=r"(addr) : "l"(smem_ptr));
    return addr;
}

#define LDSM_X4(r0, r1, r2, r3, addr) \
    asm volatile("ldmatrix.sync.aligned.m8n8.x4.shared.b16 {%0,%1,%2,%3}, [%4];" \
        : "=r"(r0), "=r"(r1), "=r"(r2), "=r"(r3) : "r"(addr))

#define MMA16816(c, a, b0, b1) \
    asm volatile("mma.sync.aligned.m16n8k16.row.col.f32.bf16.bf16.f32 " \
        "{%0,%1,%2,%3},{%4,%5,%6,%7},{%8,%9},{%0,%1,%2,%3};" \
        : "+f"((c)[0]), "+f"((c)[1]), "+f"((c)[2]), "+f"((c)[3]) \
        : "r"((a)[0]), "r"((a)[1]), "r"((a)[2]), "r"((a)[3]), "r"(b0), "r"(b1))

#define CP_ASYNC16(smaddr, gptr) \
    asm volatile("cp.async.cg.shared.global [%0], [%1], 16;" \
        :: "r"(smaddr), "l"(gptr))
#define CP_COMMIT() asm volatile("cp.async.commit_group;" ::: "memory")
#define CP_WAIT0()  asm volatile("cp.async.wait_group 0;" ::: "memory")
#define CP_WAIT1()  asm volatile("cp.async.wait_group 1;" ::: "memory")

// ===========================================================================
// Scratch (device globals)
// ===========================================================================
__device__ float g_Q[SEQ * DM];
__device__ float g_K[SEQ * DM];
__device__ float g_V[SEQ * DM];
__device__ float g_CTX[SEQ * DM];
__device__ float g_OUT[SEQ * DM];
__device__ float g_ATTN[(size_t)NH * SEQ * SEQ];

// bf16 hi/lo split scratch (reused across phases)
__device__ __nv_bfloat16 g_qh[SEQ * DM],  g_ql[SEQ * DM];
__device__ __nv_bfloat16 g_kh[SEQ * DM],  g_kl[SEQ * DM];
__device__ __nv_bfloat16 g_vh[SEQ * DM],  g_vl[SEQ * DM];   // later: V^T per head [NH][64][SEQ]
__device__ __nv_bfloat16 g_ch[SEQ * DM],  g_cl[SEQ * DM];
__device__ __nv_bfloat16 g_Wqh[DM * DM], g_Wql[DM * DM];
__device__ __nv_bfloat16 g_Wkh[DM * DM], g_Wkl[DM * DM];
__device__ __nv_bfloat16 g_Wvh[DM * DM], g_Wvl[DM * DM];
__device__ __nv_bfloat16 g_Woh[DM * DM], g_Wol[DM * DM];

// split softmax probabilities (hi/lo bf16)
__device__ __nv_bfloat16 g_Ph[(size_t)NH * SEQ * SEQ];
__device__ __nv_bfloat16 g_Pl[(size_t)NH * SEQ * SEQ];

// ===========================================================================
// Split-precision prep: x -> (bf16 hi, bf16 lo)
// ===========================================================================
struct PrepBatch {
    const float* src[8];
    __nv_bfloat16* hi[8];
    __nv_bfloat16* lo[8];
    int n4[8];
};

__global__ __launch_bounds__(256) void split_prep(PrepBatch pb)
{
    int z = blockIdx.z;
    int i = blockIdx.x * 256 + threadIdx.x;
    if (i >= pb.n4[z]) return;
    float4 v = ((const float4*)pb.src[z])[i];
    __nv_bfloat16 h0 = __float2bfloat16(v.x);
    __nv_bfloat16 h1 = __float2bfloat16(v.y);
    __nv_bfloat16 h2 = __float2bfloat16(v.z);
    __nv_bfloat16 h3 = __float2bfloat16(v.w);
    __nv_bfloat16 l0 = __float2bfloat16(v.x - __bfloat162float(h0));
    __nv_bfloat16 l1 = __float2bfloat16(v.y - __bfloat162float(h1));
    __nv_bfloat16 l2 = __float2bfloat16(v.z - __bfloat162float(h2));
    __nv_bfloat16 l3 = __float2bfloat16(v.w - __bfloat162float(h3));
    __nv_bfloat162* hp = (__nv_bfloat162*)pb.hi[z];
    __nv_bfloat162* lp = (__nv_bfloat162*)pb.lo[z];
    hp[2 * i]     = __nv_bfloat162(h0, h1);
    hp[2 * i + 1] = __nv_bfloat162(h2, h3);
    lp[2 * i]     = __nv_bfloat162(l0, l1);
    lp[2 * i + 1] = __nv_bfloat162(l2, l3);
}

// ===========================================================================
// V transpose + split: g_V[k][h*64+d] -> Vth/Vtl [h][d][k]  (bf16 hi/lo)
// grid (SEQ/128, NH), 256 threads
// ===========================================================================
__global__ __launch_bounds__(256) void vtrans_split(const float* __restrict__ V,
                                                    __nv_bfloat16* __restrict__ Vth,
                                                    __nv_bfloat16* __restrict__ Vtl)
{
    __shared__ float sT[64][132];
    const int h  = blockIdx.y;
    const int k0 = blockIdx.x * 128;
    const int tid = threadIdx.x;

    // load 128 k-rows x 64 dims, transposing into sT[d][k]
#pragma unroll
    for (int i = 0; i < 8; ++i) {
        int idx = tid + i * 256;          // 0..2047 float4s
        int r   = idx >> 4;               // k row 0..127
        int c4  = idx & 15;               // float4 within row
        float4 v = *(const float4*)&V[(size_t)(k0 + r) * DM + h * DKH + c4 * 4];
        sT[c4 * 4 + 0][r] = v.x;
        sT[c4 * 4 + 1][r] = v.y;
        sT[c4 * 4 + 2][r] = v.z;
        sT[c4 * 4 + 3][r] = v.w;
    }
    __syncthreads();

    const int d  = tid >> 2;
    const int kg = (tid & 3) * 32;
    size_t base = ((size_t)h * DKH + d) * SEQ + k0 + kg;
#pragma unroll 8
    for (int i = 0; i < 32; ++i) {
        float val = sT[d][kg + i];
        __nv_bfloat16 hi = __float2bfloat16(val);
        __nv_bfloat16 lo = __float2bfloat16(val - __bfloat162float(hi));
        Vth[base + i] = hi;
        Vtl[base + i] = lo;
    }
}

// ===========================================================================
// mma.sync split-bf16 GEMM: C[M,N] = A[M,K] @ W[N,K]^T + bias[N]
// (unchanged from R4, validated)
// ===========================================================================
#define GP 40
#define TILE_B (128 * GP * 2)
#define STAGE_B (4 * TILE_B)
#define GEMM_SMEM (2 * STAGE_B)

struct GemmPtrs {
    const __nv_bfloat16 *Ah, *Al, *Bh, *Bl;
    const float* bias;
    float* C;
};
struct GemmBatch { GemmPtrs g[3]; };

__global__ __launch_bounds__(256) void gemm_mma(GemmBatch batch)
{
    GemmPtrs gp = batch.g[blockIdx.z];
    extern __shared__ char smem[];
    uint32_t sb = smem_to_u32(smem);

    const int tid  = threadIdx.x;
    const int lane = tid & 31;
    const int wid  = tid >> 5;
    const int wm   = wid >> 1;
    const int wn   = wid & 1;
    const int bm   = blockIdx.y * 128;
    const int bn   = blockIdx.x * 128;

    const __nv_bfloat16* tp[4] = { gp.Ah, gp.Al, gp.Bh, gp.Bl };

    float acc[2][8][4];
#pragma unroll
    for (int i = 0; i < 2; ++i)
#pragma unroll
        for (int j = 0; j < 8; ++j)
#pragma unroll
            for (int c = 0; c < 4; ++c) acc[i][j][c] = 0.f;

    auto issue_stage = [&](int it, int s) {
#pragma unroll
        for (int j = 0; j < 8; ++j) {
            int c2  = tid + j * 256;
            int tt  = c2 >> 9;
            int idx = c2 & 511;
            int r   = idx >> 2;
            int c   = idx & 3;
            uint32_t sm = sb + (uint32_t)(s * STAGE_B + tt * TILE_B + r * 80 + c * 16);
            int grow = ((tt < 2) ? bm : bn) + r;
            const __nv_bfloat16* g8 = tp[tt] + (size_t)grow * DM + it * 32 + c * 8;
            CP_ASYNC16(sm, g8);
        }
        CP_COMMIT();
    };

    issue_stage(0, 0);

    for (int it = 0; it < DM / 32; ++it) {
        const int s = it & 1;
        if (it + 1 < DM / 32) { issue_stage(it + 1, (it + 1) & 1); CP_WAIT1(); }
        else                  { CP_WAIT0(); }
        __syncthreads();

        const uint32_t base = sb + s * STAGE_B;
        const uint32_t aH = base;
        const uint32_t aL = base + TILE_B;
        const uint32_t bH = base + 2 * TILE_B;
        const uint32_t bL = base + 3 * TILE_B;

#pragma unroll
        for (int ks = 0; ks < 2; ++ks) {
            const uint32_t aoff = (uint32_t)((wm * 32 + (lane & 15)) * 80 + ks * 32 + (lane >> 4) * 16);
            uint32_t ah0[4], ah1[4], al0[4], al1[4];
            LDSM_X4(ah0[0], ah0[1], ah0[2], ah0[3], aH + aoff);
            LDSM_X4(ah1[0], ah1[1], ah1[2], ah1[3], aH + aoff + 16 * 80);
            LDSM_X4(al0[0], al0[1], al0[2], al0[3], aL + aoff);
            LDSM_X4(al1[0], al1[1], al1[2], al1[3], aL + aoff + 16 * 80);

            const int brow = (lane & 7) + ((lane >> 4) << 3);
            const uint32_t bko = (uint32_t)(ks * 32 + ((lane >> 3) & 1) * 16);
            uint32_t bh[4][4], bl[4][4];
#pragma unroll
            for (int p = 0; p < 4; ++p) {
                uint32_t boff = (uint32_t)((wn * 64 + p * 16 + brow) * 80) + bko;
                LDSM_X4(bh[p][0], bh[p][1], bh[p][2], bh[p][3], bH + boff);
                LDSM_X4(bl[p][0], bl[p][1], bl[p][2], bl[p][3], bL + boff);
            }

#pragma unroll
            for (int mf = 0; mf < 2; ++mf) {
                const uint32_t* Ah_ = mf ? ah1 : ah0;
                const uint32_t* Al_ = mf ? al1 : al0;
#pragma unroll
                for (int p = 0; p < 4; ++p) {
                    MMA16816(acc[mf][2 * p],     Ah_, bh[p][0], bh[p][1]);
                    MMA16816(acc[mf][2 * p + 1], Ah_, bh[p][2], bh[p][3]);
                    MMA16816(acc[mf][2 * p],     Ah_, bl[p][0], bl[p][1]);
                    MMA16816(acc[mf][2 * p + 1], Ah_, bl[p][2], bl[p][3]);
                    MMA16816(acc[mf][2 * p],     Al_, bh[p][0], bh[p][1]);
                    MMA16816(acc[mf][2 * p + 1], Al_, bh[p][2], bh[p][3]);
                }
            }
        }
        __syncthreads();
    }

    const int l4 = lane >> 2;
    const int l2 = (lane & 3) * 2;
#pragma unroll
    for (int mf = 0; mf < 2; ++mf) {
        int r0 = bm + wm * 32 + mf * 16 + l4;
#pragma unroll
        for (int nf = 0; nf < 8; ++nf) {
            int col = bn + wn * 64 + nf * 8 + l2;
            float2 bb = *(const float2*)&gp.bias[col];
            float2 v0 = { acc[mf][nf][0] + bb.x, acc[mf][nf][1] + bb.y };
            float2 v1 = { acc[mf][nf][2] + bb.x, acc[mf][nf][3] + bb.y };
            *(float2*)&gp.C[(size_t)r0 * DM + col]       = v0;
            *(float2*)&gp.C[(size_t)(r0 + 8) * DM + col] = v1;
        }
    }
}

// ===========================================================================
// K1: scores + softmax. Block = (head, 16 q-rows).
// S = scale*(Qh*Kh^T + Qh*Kl^T + Ql*Kh^T) via mma; softmax in smem;
// writes attn fp32 + split P (bf16 hi/lo) to global.
// smem: QH 2304 | QL 2304 | K stages 2*36864 | S 131072 | mask 8192 = 217600 B
// ===========================================================================
#define K1_QPITCH 144           // bytes (72 bf16)
#define K1_OFF_QH 0
#define K1_OFF_QL 2304
#define K1_OFF_K  4608
#define K1_KSTAGE 36864         // KH(18432) + KL(18432)
#define K1_OFF_S  (K1_OFF_K + 2 * K1_KSTAGE)       // 78336
#define K1_OFF_M  (K1_OFF_S + 16 * SEQ * 4)        // 209408
#define K1_SMEM   (K1_OFF_M + SEQ * 4)             // 217600

__global__ __launch_bounds__(256) void attn_scores(
    const __nv_bfloat16* __restrict__ Qh, const __nv_bfloat16* __restrict__ Ql,
    const __nv_bfloat16* __restrict__ Kh, const __nv_bfloat16* __restrict__ Kl,
    const int* __restrict__ mask,
    float* __restrict__ attn,
    __nv_bfloat16* __restrict__ Ph, __nv_bfloat16* __restrict__ Pl)
{
    extern __shared__ char smem[];
    uint32_t sb = smem_to_u32(smem);
    float* sS = (float*)(smem + K1_OFF_S);
    int*   sM = (int*)(smem + K1_OFF_M);

    const int h    = blockIdx.y;
    const int q0   = blockIdx.x * 16;
    const int tid  = threadIdx.x;
    const int lane = tid & 31;
    const int wid  = tid >> 5;

    // stage Q (16 rows x 64 dims, hi+lo) and mask
    {
        int mat = tid >> 7;          // 0 = hi, 1 = lo
        int idx = tid & 127;
        int r = idx >> 3, c = idx & 7;
        const __nv_bfloat16* src = (mat ? Ql : Qh) + (size_t)(q0 + r) * DM + h * DKH + c * 8;
        *(uint4*)(smem + (mat ? K1_OFF_QL : K1_OFF_QH) + r * K1_QPITCH + c * 16) =
            *(const uint4*)src;
#pragma unroll
        for (int i = 0; i < 8; ++i) sM[tid + i * 256] = mask[tid + i * 256];
    }

    auto issue_stage = [&](int kt, int s) {
#pragma unroll
        for (int j = 0; j < 8; ++j) {
            int c2  = tid + j * 256;      // 0..2047
            int mat = c2 >> 10;
            int idx = c2 & 1023;
            int r = idx >> 3, c = idx & 7;
            uint32_t sm = sb + (uint32_t)(K1_OFF_K + s * K1_KSTAGE + mat * 18432 + r * K1_QPITCH + c * 16);
            const __nv_bfloat16* g8 = (mat ? Kl : Kh) + (size_t)(kt * 128 + r) * DM + h * DKH + c * 8;
            CP_ASYNC16(sm, g8);
        }
        CP_COMMIT();
    };

    issue_stage(0, 0);
    __syncthreads();   // Q + mask visible

    // preload A fragments (shared M=16 across all warps)
    uint32_t aH[4][4], aL[4][4];
#pragma unroll
    for (int ks = 0; ks < 4; ++ks) {
        uint32_t aoff = (uint32_t)((lane & 15) * K1_QPITCH + ks * 32 + (lane >> 4) * 16);
        LDSM_X4(aH[ks][0], aH[ks][1], aH[ks][2], aH[ks][3], sb + K1_OFF_QH + aoff);
        LDSM_X4(aL[ks][0], aL[ks][1], aL[ks][2], aL[ks][3], sb + K1_OFF_QL + aoff);
    }

    const int brow = (lane & 7) + ((lane >> 4) << 3);
    const int r0 = lane >> 2;
    const int c0 = (lane & 3) * 2;

    for (int kt = 0; kt < SEQ / 128; ++kt) {
        const int s = kt & 1;
        if (kt + 1 < SEQ / 128) { issue_stage(kt + 1, s ^ 1); CP_WAIT1(); }
        else                    { CP_WAIT0(); }
        __syncthreads();

        const uint32_t kH = sb + K1_OFF_K + s * K1_KSTAGE;
        const uint32_t kL = kH + 18432;

        float acc[2][4] = {{0.f,0.f,0.f,0.f},{0.f,0.f,0.f,0.f}};
#pragma unroll
        for (int ks = 0; ks < 4; ++ks) {
            uint32_t boff = (uint32_t)((wid * 16 + brow) * K1_QPITCH + ks * 32 + ((lane >> 3) & 1) * 16);
            uint32_t bh0, bh1, bh2, bh3, bl0, bl1, bl2, bl3;
            LDSM_X4(bh0, bh1, bh2, bh3, kH + boff);
            LDSM_X4(bl0, bl1, bl2, bl3, kL + boff);
            MMA16816(acc[0], aH[ks], bh0, bh1);
            MMA16816(acc[1], aH[ks], bh2, bh3);
            MMA16816(acc[0], aH[ks], bl0, bl1);
            MMA16816(acc[1], aH[ks], bl2, bl3);
            MMA16816(acc[0], aL[ks], bh0, bh1);
            MMA16816(acc[1], aL[ks], bh2, bh3);
        }

        // epilogue: scale + mask -> sS (cols = global key index)
#pragma unroll
        for (int t8 = 0; t8 < 2; ++t8) {
            int key = kt * 128 + wid * 16 + t8 * 8 + c0;
            bool m0 = sM[key] != 0, m1 = sM[key + 1] != 0;
            sS[r0 * SEQ + key]           = m0 ? acc[t8][0] * 0.125f : -1e9f;
            sS[r0 * SEQ + key + 1]       = m1 ? acc[t8][1] * 0.125f : -1e9f;
            sS[(r0 + 8) * SEQ + key]     = m0 ? acc[t8][2] * 0.125f : -1e9f;
            sS[(r0 + 8) * SEQ + key + 1] = m1 ? acc[t8][3] * 0.125f : -1e9f;
        }
        __syncthreads();
    }

    // softmax: 8 warps x 2 rows
    for (int r = wid * 2; r < wid * 2 + 2; ++r) {
        float* row = &sS[r * SEQ];
        float m = -INFINITY;
        for (int j = lane; j < SEQ; j += 32) m = fmaxf(m, row[j]);
#pragma unroll
        for (int o = 16; o; o >>= 1) m = fmaxf(m, __shfl_xor_sync(0xffffffffu, m, o));
        float sum = 0.f;
        for (int j = lane; j < SEQ; j += 32) {
            float e = __expf(row[j] - m);
            row[j] = e;
            sum += e;
        }
#pragma unroll
        for (int o = 16; o; o >>= 1) sum += __shfl_xor_sync(0xffffffffu, sum, o);
        float inv = 1.0f / sum;

        size_t base = ((size_t)h * SEQ + (q0 + r)) * SEQ;
        float* gattn = attn + base;
        for (int j = lane * 4; j < SEQ; j += 128) {
            float4 p = *(float4*)&row[j];
            p.x *= inv; p.y *= inv; p.z *= inv; p.w *= inv;
            *(float4*)&gattn[j] = p;
            __nv_bfloat16 h0 = __float2bfloat16(p.x), h1 = __float2bfloat16(p.y);
            __nv_bfloat16 h2 = __float2bfloat16(p.z), h3 = __float2bfloat16(p.w);
            __nv_bfloat16 l0 = __float2bfloat16(p.x - __bfloat162float(h0));
            __nv_bfloat16 l1 = __float2bfloat16(p.y - __bfloat162float(h1));
            __nv_bfloat16 l2 = __float2bfloat16(p.z - __bfloat162float(h2));
            __nv_bfloat16 l3 = __float2bfloat16(p.w - __bfloat162float(h3));
            *(__nv_bfloat162*)&Ph[base + j]     = __nv_bfloat162(h0, h1);
            *(__nv_bfloat162*)&Ph[base + j + 2] = __nv_bfloat162(h2, h3);
            *(__nv_bfloat162*)&Pl[base + j]     = __nv_bfloat162(l0, l1);
            *(__nv_bfloat162*)&Pl[base + j + 2] = __nv_bfloat162(l2, l3);
        }
    }
}

// ===========================================================================
// K2: ctx = P @ V.  Per head: M=2048(q), N=64(d), K=2048(keys).
// Block = (128 q-rows, head). A = Ph/Pl [q][k], B = Vth/Vtl [d][k].
// ===========================================================================
#define PV_ATILE (128 * GP * 2)         // 10240 B
#define PV_BTILE (64 * GP * 2)          // 5120 B
#define PV_STAGE (2 * PV_ATILE + 2 * PV_BTILE)   // 30720 B
#define PV_SMEM  (2 * PV_STAGE)                  // 61440 B

__global__ __launch_bounds__(256) void attn_pv(
    const __nv_bfloat16* __restrict__ Ph, const __nv_bfloat16* __restrict__ Pl,
    const __nv_bfloat16* __restrict__ Vth, const __nv_bfloat16* __restrict__ Vtl,
    float* __restrict__ ctx)
{
    extern __shared__ char smem[];
    uint32_t sb = smem_to_u32(smem);

    const int tid  = threadIdx.x;
    const int lane = tid & 31;
    const int wid  = tid >> 5;
    const int wm   = wid >> 1;       // 0..3 (32 q-rows)
    const int wn   = wid & 1;        // 0..1 (32 dims)
    const int h    = blockIdx.y;
    const int bm   = blockIdx.x * 128;

    float acc[2][4][4];
#pragma unroll
    for (int i = 0; i < 2; ++i)
#pragma unroll
        for (int j = 0; j < 4; ++j)
#pragma unroll
            for (int c = 0; c < 4; ++c) acc[i][j][c] = 0.f;

    auto issue_stage = [&](int it, int s) {
#pragma unroll
        for (int j = 0; j < 6; ++j) {
            int c2 = tid + j * 256;       // 0..1535
            uint32_t sm;
            const __nv_bfloat16* g8;
            if (c2 < 1024) {
                int mat = c2 >> 9;        // 0=Ph 1=Pl
                int idx = c2 & 511;
                int r = idx >> 2, c = idx & 3;
                sm = sb + (uint32_t)(s * PV_STAGE + mat * PV_ATILE + r * 80 + c * 16);
                g8 = (mat ? Pl : Ph) + ((size_t)h * SEQ + bm + r) * SEQ + it * 32 + c * 8;
            } else {
                int c2b = c2 - 1024;
                int mat = c2b >> 8;       // 0=Vth 1=Vtl
                int idx = c2b & 255;
                int r = idx >> 2, c = idx & 3;
                sm = sb + (uint32_t)(s * PV_STAGE + 2 * PV_ATILE + mat * PV_BTILE + r * 80 + c * 16);
                g8 = (mat ? Vtl : Vth) + ((size_t)h * DKH + r) * SEQ + it * 32 + c * 8;
            }
            CP_ASYNC16(sm, g8);
        }
        CP_COMMIT();
    };

    issue_stage(0, 0);

    const int brow = (lane & 7) + ((lane >> 4) << 3);

    for (int it = 0; it < SEQ / 32; ++it) {
        const int s = it & 1;
        if (it + 1 < SEQ / 32) { issue_stage(it + 1, s ^ 1); CP_WAIT1(); }
        else                   { CP_WAIT0(); }
        __syncthreads();

        const uint32_t base = sb + s * PV_STAGE;
        const uint32_t aH = base;
        const uint32_t aL = base + PV_ATILE;
        const uint32_t bH = base + 2 * PV_ATILE;
        const uint32_t bL = bH + PV_BTILE;

#pragma unroll
        for (int ks = 0; ks < 2; ++ks) {
            uint32_t aoff = (uint32_t)((wm * 32 + (lane & 15)) * 80 + ks * 32 + (lane >> 4) * 16);
            uint32_t ah0[4], ah1[4], al0[4], al1[4];
            LDSM_X4(ah0[0], ah0[1], ah0[2], ah0[3], aH + aoff);
            LDSM_X4(ah1[0], ah1[1], ah1[2], ah1[3], aH + aoff + 16 * 80);
            LDSM_X4(al0[0], al0[1], al0[2], al0[3], aL + aoff);
            LDSM_X4(al1[0], al1[1], al1[2], al1[3], aL + aoff + 16 * 80);

            uint32_t bko = (uint32_t)(ks * 32 + ((lane >> 3) & 1) * 16);
            uint32_t bh[2][4], bl[2][4];
#pragma unroll
            for (int p = 0; p < 2; ++p) {
                uint32_t boff = (uint32_t)((wn * 32 + p * 16 + brow) * 80) + bko;
                LDSM_X4(bh[p][0], bh[p][1], bh[p][2], bh[p][3], bH + boff);
                LDSM_X4(bl[p][0], bl[p][1], bl[p][2], bl[p][3], bL + boff);
            }

#pragma unroll
            for (int mf = 0; mf < 2; ++mf) {
                const uint32_t* Ah_ = mf ? ah1 : ah0;
                const uint32_t* Al_ = mf ? al1 : al0;
#pragma unroll
                for (int p = 0; p < 2; ++p) {
                    MMA16816(acc[mf][2 * p],     Ah_, bh[p][0], bh[p][1]);
                    MMA16816(acc[mf][2 * p + 1], Ah_, bh[p][2], bh[p][3]);
                    MMA16816(acc[mf][2 * p],     Ah_, bl[p][0], bl[p][1]);
                    MMA16816(acc[mf][2 * p + 1], Ah_, bl[p][2], bl[p][3]);
                    MMA16816(acc[mf][2 * p],     Al_, bh[p][0], bh[p][1]);
                    MMA16816(acc[mf][2 * p + 1], Al_, bh[p][2], bh[p][3]);
                }
            }
        }
        __syncthreads();
    }

    const int l4 = lane >> 2;
    const int l2 = (lane & 3) * 2;
#pragma unroll
    for (int mf = 0; mf < 2; ++mf) {
        int q = bm + wm * 32 + mf * 16 + l4;
#pragma unroll
        for (int nf = 0; nf < 4; ++nf) {
            int col = h * DKH + wn * 32 + nf * 8 + l2;
            float2 v0 = { acc[mf][nf][0], acc[mf][nf][1] };
            float2 v1 = { acc[mf][nf][2], acc[mf][nf][3] };
            *(float2*)&ctx[(size_t)q * DM + col]       = v0;
            *(float2*)&ctx[(size_t)(q + 8) * DM + col] = v1;
        }
    }
}

// ===========================================================================
extern "C" void kernel_launch(void* const* d_in, const int* in_sizes, int n_in,
                              void* d_out, int out_size)
{
    const float* q    = (const float*)d_in[0];
    const float* k    = (const float*)d_in[1];
    const float* v    = (const float*)d_in[2];
    const int*   mask = (const int*)  d_in[3];
    const float* Wq   = (const float*)d_in[4];
    const float* bq   = (const float*)d_in[5];
    const float* Wk   = (const float*)d_in[6];
    const float* bk   = (const float*)d_in[7];
    const float* Wv   = (const float*)d_in[8];
    const float* bv   = (const float*)d_in[9];
    const float* Wo   = (const float*)d_in[10];
    const float* bo   = (const float*)d_in[11];

    float *Qp, *Kp, *Vp, *Cp, *Ap, *Op;
    cudaGetSymbolAddress((void**)&Qp, g_Q);
    cudaGetSymbolAddress((void**)&Kp, g_K);
    cudaGetSymbolAddress((void**)&Vp, g_V);
    cudaGetSymbolAddress((void**)&Cp, g_CTX);
    cudaGetSymbolAddress((void**)&Ap, g_ATTN);
    cudaGetSymbolAddress((void**)&Op, g_OUT);

    __nv_bfloat16 *qh, *ql, *kh, *kl, *vh, *vl, *ch, *cl, *Php, *Plp;
    __nv_bfloat16 *Wqh, *Wql, *Wkh, *Wkl, *Wvh, *Wvl, *Woh, *Wol;
    cudaGetSymbolAddress((void**)&qh, g_qh);   cudaGetSymbolAddress((void**)&ql, g_ql);
    cudaGetSymbolAddress((void**)&kh, g_kh);   cudaGetSymbolAddress((void**)&kl, g_kl);
    cudaGetSymbolAddress((void**)&vh, g_vh);   cudaGetSymbolAddress((void**)&vl, g_vl);
    cudaGetSymbolAddress((void**)&ch, g_ch);   cudaGetSymbolAddress((void**)&cl, g_cl);
    cudaGetSymbolAddress((void**)&Php, g_Ph);  cudaGetSymbolAddress((void**)&Plp, g_Pl);
    cudaGetSymbolAddress((void**)&Wqh, g_Wqh); cudaGetSymbolAddress((void**)&Wql, g_Wql);
    cudaGetSymbolAddress((void**)&Wkh, g_Wkh); cudaGetSymbolAddress((void**)&Wkl, g_Wkl);
    cudaGetSymbolAddress((void**)&Wvh, g_Wvh); cudaGetSymbolAddress((void**)&Wvl, g_Wvl);
    cudaGetSymbolAddress((void**)&Woh, g_Woh); cudaGetSymbolAddress((void**)&Wol, g_Wol);

    const size_t OUT_ELEMS  = (size_t)SEQ * DM;
    const size_t ATTN_ELEMS = (size_t)NH * SEQ * SEQ;

    float* outp = (float*)d_out;
    float* attnp;
    if ((size_t)out_size >= OUT_ELEMS + ATTN_ELEMS) {
        attnp = outp + OUT_ELEMS;
    } else if ((size_t)out_size == ATTN_ELEMS) {
        attnp = (float*)d_out;
        outp  = Op;
    } else {
        attnp = Ap;
    }

    cudaFuncSetAttribute(gemm_mma,
                         cudaFuncAttributeMaxDynamicSharedMemorySize, GEMM_SMEM);
    cudaFuncSetAttribute(attn_scores,
                         cudaFuncAttributeMaxDynamicSharedMemorySize, K1_SMEM);
    cudaFuncSetAttribute(attn_pv,
                         cudaFuncAttributeMaxDynamicSharedMemorySize, PV_SMEM);

    // 1) split inputs + weights
    {
        PrepBatch pb;
        pb.src[0] = q;  pb.hi[0] = qh;  pb.lo[0] = ql;  pb.n4[0] = SEQ * DM / 4;
        pb.src[1] = k;  pb.hi[1] = kh;  pb.lo[1] = kl;  pb.n4[1] = SEQ * DM / 4;
        pb.src[2] = v;  pb.hi[2] = vh;  pb.lo[2] = vl;  pb.n4[2] = SEQ * DM / 4;
        pb.src[3] = Wq; pb.hi[3] = Wqh; pb.lo[3] = Wql; pb.n4[3] = DM * DM / 4;
        pb.src[4] = Wk; pb.hi[4] = Wkh; pb.lo[4] = Wkl; pb.n4[4] = DM * DM / 4;
        pb.src[5] = Wv; pb.hi[5] = Wvh; pb.lo[5] = Wvl; pb.n4[5] = DM * DM / 4;
        pb.src[6] = Wo; pb.hi[6] = Woh; pb.lo[6] = Wol; pb.n4[6] = DM * DM / 4;
        pb.src[7] = q;  pb.hi[7] = qh;  pb.lo[7] = ql;  pb.n4[7] = 0;
        dim3 pg((SEQ * DM / 4 + 255) / 256, 1, 7);
        split_prep<<<pg, 256>>>(pb);
    }

    // 2) Q/K/V projections
    {
        GemmBatch gb;
        gb.g[0] = { qh, ql, Wqh, Wql, bq, Qp };
        gb.g[1] = { kh, kl, Wkh, Wkl, bk, Kp };
        gb.g[2] = { vh, vl, Wvh, Wvl, bv, Vp };
        gemm_mma<<<dim3(DM / 128, SEQ / 128, 3), 256, GEMM_SMEM>>>(gb);
    }

    // 3) split projected Q, K (overwrites input splits; safe — projections done)
    {
        PrepBatch pb;
        pb.src[0] = Qp; pb.hi[0] = qh; pb.lo[0] = ql; pb.n4[0] = SEQ * DM / 4;
        pb.src[1] = Kp; pb.hi[1] = kh; pb.lo[1] = kl; pb.n4[1] = SEQ * DM / 4;
        for (int i = 2; i < 8; ++i) { pb.src[i] = Qp; pb.hi[i] = qh; pb.lo[i] = ql; pb.n4[i] = 0; }
        dim3 pg((SEQ * DM / 4 + 255) / 256, 1, 2);
        split_prep<<<pg, 256>>>(pb);
        vtrans_split<<<dim3(SEQ / 128, NH), 256>>>(Vp, vh, vl);
    }

    // 4) scores + softmax (tensor cores)
    attn_scores<<<dim3(SEQ / 16, NH), 256, K1_SMEM>>>(qh, ql, kh, kl, mask, attnp, Php, Plp);

    // 5) ctx = P @ V (tensor cores)
    attn_pv<<<dim3(SEQ / 128, NH), 256, PV_SMEM>>>(Php, Plp, vh, vl, Cp);

    // 6) split ctx + output projection
    {
        PrepBatch pb;
        pb.src[0] = Cp; pb.hi[0] = ch; pb.lo[0] = cl; pb.n4[0] = SEQ * DM / 4;
        for (int i = 1; i < 8; ++i) { pb.src[i] = Cp; pb.hi[i] = ch; pb.lo[i] = cl; pb.n4[i] = 0; }
        dim3 pg((SEQ * DM / 4 + 255) / 256, 1, 1);
        split_prep<<<pg, 256>>>(pb);

        GemmBatch gb;
        gb.g[0] = { ch, cl, Woh, Wol, bo, outp };
        gb.g[1] = gb.g[0];
        gb.g[2] = gb.g[0];
        gemm_mma<<<dim3(DM / 128, SEQ / 128, 1), 256, GEMM_SMEM>>>(gb);
    }
}

// round 6
// speedup vs baseline: 3.7462x; 1.2208x over previous
#include <cuda_runtime.h>
#include <cuda_bf16.h>
#include <math.h>
#include <stdint.h>

// Problem constants
#define SEQ 2048
#define DM  1024
#define NH  16
#define DKH 64

// ===========================================================================
// Portable PTX helpers (base compute_103 target: NO tcgen05 anywhere)
// ===========================================================================
__device__ __forceinline__ uint32_t smem_to_u32(const void* smem_ptr) {
    uint32_t addr;
    asm("{ .reg .u64 tmp; cvta.to.shared.u64 tmp, %1; cvt.u32.u64 %0, tmp; }"
        : "=r"(addr) : "l"(smem_ptr));
    return addr;
}

#define LDSM_X4(r0, r1, r2, r3, addr) \
    asm volatile("ldmatrix.sync.aligned.m8n8.x4.shared.b16 {%0,%1,%2,%3}, [%4];" \
        : "=r"(r0), "=r"(r1), "=r"(r2), "=r"(r3) : "r"(addr))

#define LDSM_X4T(r0, r1, r2, r3, addr) \
    asm volatile("ldmatrix.sync.aligned.m8n8.x4.trans.shared.b16 {%0,%1,%2,%3}, [%4];" \
        : "=r"(r0), "=r"(r1), "=r"(r2), "=r"(r3) : "r"(addr))

#define MMA16816(c, a, b0, b1) \
    asm volatile("mma.sync.aligned.m16n8k16.row.col.f32.bf16.bf16.f32 " \
        "{%0,%1,%2,%3},{%4,%5,%6,%7},{%8,%9},{%0,%1,%2,%3};" \
        : "+f"((c)[0]), "+f"((c)[1]), "+f"((c)[2]), "+f"((c)[3]) \
        : "r"((a)[0]), "r"((a)[1]), "r"((a)[2]), "r"((a)[3]), "r"(b0), "r"(b1))

#define CP_ASYNC16(smaddr, gptr) \
    asm volatile("cp.async.cg.shared.global [%0], [%1], 16;" \
        :: "r"(smaddr), "l"(gptr))
#define CP_COMMIT() asm volatile("cp.async.commit_group;" ::: "memory")
#define CP_WAIT0()  asm volatile("cp.async.wait_group 0;" ::: "memory")
#define CP_WAIT1()  asm volatile("cp.async.wait_group 1;" ::: "memory")

// ===========================================================================
// Scratch (device globals)
// ===========================================================================
__device__ float g_Q[SEQ * DM];
__device__ float g_K[SEQ * DM];
__device__ float g_V[SEQ * DM];
__device__ float g_CTX[SEQ * DM];
__device__ float g_OUT[SEQ * DM];
__device__ float g_ATTN[(size_t)NH * SEQ * SEQ];

// bf16 hi/lo split scratch
__device__ __nv_bfloat16 g_qh[SEQ * DM],  g_ql[SEQ * DM];
__device__ __nv_bfloat16 g_kh[SEQ * DM],  g_kl[SEQ * DM];
__device__ __nv_bfloat16 g_vh[SEQ * DM],  g_vl[SEQ * DM];
__device__ __nv_bfloat16 g_ch[SEQ * DM],  g_cl[SEQ * DM];
__device__ __nv_bfloat16 g_Wqh[DM * DM], g_Wql[DM * DM];
__device__ __nv_bfloat16 g_Wkh[DM * DM], g_Wkl[DM * DM];
__device__ __nv_bfloat16 g_Wvh[DM * DM], g_Wvl[DM * DM];
__device__ __nv_bfloat16 g_Woh[DM * DM], g_Wol[DM * DM];

// S (scores) split storage, later P source
__device__ __nv_bfloat16 g_Sh[(size_t)NH * SEQ * SEQ];
__device__ __nv_bfloat16 g_Sl[(size_t)NH * SEQ * SEQ];

// softmax stats
__device__ float g_pmax[NH * 16 * SEQ];
__device__ float g_psum[NH * 16 * SEQ];
__device__ float g_stats[NH * SEQ * 2];

// ===========================================================================
// Split-precision prep: x -> (bf16 hi, bf16 lo)
// ===========================================================================
struct PrepBatch {
    const float* src[8];
    __nv_bfloat16* hi[8];
    __nv_bfloat16* lo[8];
    int n4[8];
};

__global__ __launch_bounds__(256) void split_prep(PrepBatch pb)
{
    int z = blockIdx.z;
    int i = blockIdx.x * 256 + threadIdx.x;
    if (i >= pb.n4[z]) return;
    float4 v = ((const float4*)pb.src[z])[i];
    __nv_bfloat16 h0 = __float2bfloat16(v.x);
    __nv_bfloat16 h1 = __float2bfloat16(v.y);
    __nv_bfloat16 h2 = __float2bfloat16(v.z);
    __nv_bfloat16 h3 = __float2bfloat16(v.w);
    __nv_bfloat16 l0 = __float2bfloat16(v.x - __bfloat162float(h0));
    __nv_bfloat16 l1 = __float2bfloat16(v.y - __bfloat162float(h1));
    __nv_bfloat16 l2 = __float2bfloat16(v.z - __bfloat162float(h2));
    __nv_bfloat16 l3 = __float2bfloat16(v.w - __bfloat162float(h3));
    __nv_bfloat162* hp = (__nv_bfloat162*)pb.hi[z];
    __nv_bfloat162* lp = (__nv_bfloat162*)pb.lo[z];
    hp[2 * i]     = __nv_bfloat162(h0, h1);
    hp[2 * i + 1] = __nv_bfloat162(h2, h3);
    lp[2 * i]     = __nv_bfloat162(l0, l1);
    lp[2 * i + 1] = __nv_bfloat162(l2, l3);
}

// ===========================================================================
// mma.sync split-bf16 GEMM: C[M,N] = A[M,K] @ W[N,K]^T + bias[N]  (validated)
// ===========================================================================
#define GP 40
#define TILE_B (128 * GP * 2)
#define STAGE_B (4 * TILE_B)
#define GEMM_SMEM (2 * STAGE_B)

struct GemmPtrs {
    const __nv_bfloat16 *Ah, *Al, *Bh, *Bl;
    const float* bias;
    float* C;
};
struct GemmBatch { GemmPtrs g[3]; };

__global__ __launch_bounds__(256) void gemm_mma(GemmBatch batch)
{
    GemmPtrs gp = batch.g[blockIdx.z];
    extern __shared__ char smem[];
    uint32_t sb = smem_to_u32(smem);

    const int tid  = threadIdx.x;
    const int lane = tid & 31;
    const int wid  = tid >> 5;
    const int wm   = wid >> 1;
    const int wn   = wid & 1;
    const int bm   = blockIdx.y * 128;
    const int bn   = blockIdx.x * 128;

    const __nv_bfloat16* tp[4] = { gp.Ah, gp.Al, gp.Bh, gp.Bl };

    float acc[2][8][4];
#pragma unroll
    for (int i = 0; i < 2; ++i)
#pragma unroll
        for (int j = 0; j < 8; ++j)
#pragma unroll
            for (int c = 0; c < 4; ++c) acc[i][j][c] = 0.f;

    auto issue_stage = [&](int it, int s) {
#pragma unroll
        for (int j = 0; j < 8; ++j) {
            int c2  = tid + j * 256;
            int tt  = c2 >> 9;
            int idx = c2 & 511;
            int r   = idx >> 2;
            int c   = idx & 3;
            uint32_t sm = sb + (uint32_t)(s * STAGE_B + tt * TILE_B + r * 80 + c * 16);
            int grow = ((tt < 2) ? bm : bn) + r;
            const __nv_bfloat16* g8 = tp[tt] + (size_t)grow * DM + it * 32 + c * 8;
            CP_ASYNC16(sm, g8);
        }
        CP_COMMIT();
    };

    issue_stage(0, 0);

    for (int it = 0; it < DM / 32; ++it) {
        const int s = it & 1;
        if (it + 1 < DM / 32) { issue_stage(it + 1, (it + 1) & 1); CP_WAIT1(); }
        else                  { CP_WAIT0(); }
        __syncthreads();

        const uint32_t base = sb + s * STAGE_B;
        const uint32_t aH = base;
        const uint32_t aL = base + TILE_B;
        const uint32_t bH = base + 2 * TILE_B;
        const uint32_t bL = base + 3 * TILE_B;

#pragma unroll
        for (int ks = 0; ks < 2; ++ks) {
            const uint32_t aoff = (uint32_t)((wm * 32 + (lane & 15)) * 80 + ks * 32 + (lane >> 4) * 16);
            uint32_t ah0[4], ah1[4], al0[4], al1[4];
            LDSM_X4(ah0[0], ah0[1], ah0[2], ah0[3], aH + aoff);
            LDSM_X4(ah1[0], ah1[1], ah1[2], ah1[3], aH + aoff + 16 * 80);
            LDSM_X4(al0[0], al0[1], al0[2], al0[3], aL + aoff);
            LDSM_X4(al1[0], al1[1], al1[2], al1[3], aL + aoff + 16 * 80);

            const int brow = (lane & 7) + ((lane >> 4) << 3);
            const uint32_t bko = (uint32_t)(ks * 32 + ((lane >> 3) & 1) * 16);
            uint32_t bh[4][4], bl[4][4];
#pragma unroll
            for (int p = 0; p < 4; ++p) {
                uint32_t boff = (uint32_t)((wn * 64 + p * 16 + brow) * 80) + bko;
                LDSM_X4(bh[p][0], bh[p][1], bh[p][2], bh[p][3], bH + boff);
                LDSM_X4(bl[p][0], bl[p][1], bl[p][2], bl[p][3], bL + boff);
            }

#pragma unroll
            for (int mf = 0; mf < 2; ++mf) {
                const uint32_t* Ah_ = mf ? ah1 : ah0;
                const uint32_t* Al_ = mf ? al1 : al0;
#pragma unroll
                for (int p = 0; p < 4; ++p) {
                    MMA16816(acc[mf][2 * p],     Ah_, bh[p][0], bh[p][1]);
                    MMA16816(acc[mf][2 * p + 1], Ah_, bh[p][2], bh[p][3]);
                    MMA16816(acc[mf][2 * p],     Ah_, bl[p][0], bl[p][1]);
                    MMA16816(acc[mf][2 * p + 1], Ah_, bl[p][2], bl[p][3]);
                    MMA16816(acc[mf][2 * p],     Al_, bh[p][0], bh[p][1]);
                    MMA16816(acc[mf][2 * p + 1], Al_, bh[p][2], bh[p][3]);
                }
            }
        }
        __syncthreads();
    }

    const int l4 = lane >> 2;
    const int l2 = (lane & 3) * 2;
#pragma unroll
    for (int mf = 0; mf < 2; ++mf) {
        int r0 = bm + wm * 32 + mf * 16 + l4;
#pragma unroll
        for (int nf = 0; nf < 8; ++nf) {
            int col = bn + wn * 64 + nf * 8 + l2;
            float2 bb = *(const float2*)&gp.bias[col];
            float2 v0 = { acc[mf][nf][0] + bb.x, acc[mf][nf][1] + bb.y };
            float2 v1 = { acc[mf][nf][2] + bb.x, acc[mf][nf][3] + bb.y };
            *(float2*)&gp.C[(size_t)r0 * DM + col]       = v0;
            *(float2*)&gp.C[(size_t)(r0 + 8) * DM + col] = v1;
        }
    }
}

// ===========================================================================
// attn_sgemm: S[h][q][k] (bf16 split) = scale*(Qh·Kh + Qh·Kl + Ql·Kh), masked,
// + per-(row, k-tile) partial max / expsum.
// grid (16 ktiles, 16 qtiles, 16 heads), 256 threads, single K stage (64).
// ===========================================================================
#define SG_PITCH 144
#define SG_TILE (128 * SG_PITCH)            // 18432
#define SG_OFF_MASK (4 * SG_TILE)           // 73728
#define SG_OFF_MAX  (SG_OFF_MASK + 512)     // 74240
#define SG_OFF_SUM  (SG_OFF_MAX + 1024)     // 75264
#define SG_SMEM     (SG_OFF_SUM + 1024)     // 76288

__global__ __launch_bounds__(256) void attn_sgemm(
    const __nv_bfloat16* __restrict__ Qh, const __nv_bfloat16* __restrict__ Ql,
    const __nv_bfloat16* __restrict__ Kh, const __nv_bfloat16* __restrict__ Kl,
    const int* __restrict__ mask,
    __nv_bfloat16* __restrict__ Sh, __nv_bfloat16* __restrict__ Sl,
    float* __restrict__ pmax, float* __restrict__ psum)
{
    extern __shared__ char smem[];
    uint32_t sb = smem_to_u32(smem);
    const int tid = threadIdx.x;
    const int lane = tid & 31;
    const int wid = tid >> 5;
    const int wm = wid >> 1;
    const int wn = wid & 1;
    const int h  = blockIdx.z;
    const int kb = blockIdx.x * 128;
    const int qb = blockIdx.y * 128;

    const __nv_bfloat16* mats[4] = { Qh, Ql, Kh, Kl };

#pragma unroll
    for (int j = 0; j < 16; ++j) {
        int c2  = tid + j * 256;
        int mat = c2 >> 10;
        int idx = c2 & 1023;
        int r = idx >> 3, c = idx & 7;
        uint32_t sm = sb + (uint32_t)(mat * SG_TILE + r * SG_PITCH + c * 16);
        int grow = ((mat < 2) ? qb : kb) + r;
        CP_ASYNC16(sm, mats[mat] + (size_t)grow * DM + h * DKH + c * 8);
    }
    CP_COMMIT();
    int* sMask = (int*)(smem + SG_OFF_MASK);
    if (tid < 128) sMask[tid] = mask[kb + tid];
    CP_WAIT0();
    __syncthreads();

    float acc[2][8][4];
#pragma unroll
    for (int i = 0; i < 2; ++i)
#pragma unroll
        for (int j = 0; j < 8; ++j)
#pragma unroll
            for (int c = 0; c < 4; ++c) acc[i][j][c] = 0.f;

    const uint32_t aH = sb, aL = sb + SG_TILE, bH = sb + 2 * SG_TILE, bL = sb + 3 * SG_TILE;
    const int brow = (lane & 7) + ((lane >> 4) << 3);

#pragma unroll
    for (int ks = 0; ks < 4; ++ks) {
        uint32_t aoff = (uint32_t)((wm * 32 + (lane & 15)) * SG_PITCH + ks * 32 + (lane >> 4) * 16);
        uint32_t ah0[4], ah1[4], al0[4], al1[4];
        LDSM_X4(ah0[0], ah0[1], ah0[2], ah0[3], aH + aoff);
        LDSM_X4(ah1[0], ah1[1], ah1[2], ah1[3], aH + aoff + 16 * SG_PITCH);
        LDSM_X4(al0[0], al0[1], al0[2], al0[3], aL + aoff);
        LDSM_X4(al1[0], al1[1], al1[2], al1[3], aL + aoff + 16 * SG_PITCH);

        uint32_t bko = (uint32_t)(ks * 32 + ((lane >> 3) & 1) * 16);
        uint32_t bh[4][4], bl[4][4];
#pragma unroll
        for (int p = 0; p < 4; ++p) {
            uint32_t boff = (uint32_t)((wn * 64 + p * 16 + brow) * SG_PITCH) + bko;
            LDSM_X4(bh[p][0], bh[p][1], bh[p][2], bh[p][3], bH + boff);
            LDSM_X4(bl[p][0], bl[p][1], bl[p][2], bl[p][3], bL + boff);
        }
#pragma unroll
        for (int mf = 0; mf < 2; ++mf) {
            const uint32_t* Ah_ = mf ? ah1 : ah0;
            const uint32_t* Al_ = mf ? al1 : al0;
#pragma unroll
            for (int p = 0; p < 4; ++p) {
                MMA16816(acc[mf][2 * p],     Ah_, bh[p][0], bh[p][1]);
                MMA16816(acc[mf][2 * p + 1], Ah_, bh[p][2], bh[p][3]);
                MMA16816(acc[mf][2 * p],     Ah_, bl[p][0], bl[p][1]);
                MMA16816(acc[mf][2 * p + 1], Ah_, bl[p][2], bl[p][3]);
                MMA16816(acc[mf][2 * p],     Al_, bh[p][0], bh[p][1]);
                MMA16816(acc[mf][2 * p + 1], Al_, bh[p][2], bh[p][3]);
            }
        }
    }

    // ---- epilogue: scale+mask, partial softmax stats, split-store S ----
    const int c0 = (lane & 3) * 2;
    const int r0 = lane >> 2;
#pragma unroll
    for (int mf = 0; mf < 2; ++mf)
#pragma unroll
        for (int nf = 0; nf < 8; ++nf) {
            int col = wn * 64 + nf * 8 + c0;
            bool k0 = sMask[col] != 0, k1 = sMask[col + 1] != 0;
            acc[mf][nf][0] = k0 ? acc[mf][nf][0] * 0.125f : -1e9f;
            acc[mf][nf][1] = k1 ? acc[mf][nf][1] * 0.125f : -1e9f;
            acc[mf][nf][2] = k0 ? acc[mf][nf][2] * 0.125f : -1e9f;
            acc[mf][nf][3] = k1 ? acc[mf][nf][3] * 0.125f : -1e9f;
        }

    float* sMax = (float*)(smem + SG_OFF_MAX);
    float* sSum = (float*)(smem + SG_OFF_SUM);
    float rmax[2][2];
#pragma unroll
    for (int mf = 0; mf < 2; ++mf)
#pragma unroll
        for (int hf = 0; hf < 2; ++hf) {
            float m = -INFINITY;
#pragma unroll
            for (int nf = 0; nf < 8; ++nf) {
                m = fmaxf(m, acc[mf][nf][hf * 2]);
                m = fmaxf(m, acc[mf][nf][hf * 2 + 1]);
            }
            m = fmaxf(m, __shfl_xor_sync(0xffffffffu, m, 1));
            m = fmaxf(m, __shfl_xor_sync(0xffffffffu, m, 2));
            rmax[mf][hf] = m;
            if ((lane & 3) == 0) sMax[(wm * 32 + mf * 16 + hf * 8 + r0) * 2 + wn] = m;
        }
    __syncthreads();
#pragma unroll
    for (int mf = 0; mf < 2; ++mf)
#pragma unroll
        for (int hf = 0; hf < 2; ++hf) {
            int row = wm * 32 + mf * 16 + hf * 8 + r0;
            float M = fmaxf(sMax[row * 2], sMax[row * 2 + 1]);
            rmax[mf][hf] = M;
            float s = 0.f;
#pragma unroll
            for (int nf = 0; nf < 8; ++nf) {
                s += __expf(acc[mf][nf][hf * 2] - M);
                s += __expf(acc[mf][nf][hf * 2 + 1] - M);
            }
            s += __shfl_xor_sync(0xffffffffu, s, 1);
            s += __shfl_xor_sync(0xffffffffu, s, 2);
            if ((lane & 3) == 0) sSum[row * 2 + wn] = s;
        }
    __syncthreads();
    if (wn == 0 && (lane & 3) == 0) {
#pragma unroll
        for (int mf = 0; mf < 2; ++mf)
#pragma unroll
            for (int hf = 0; hf < 2; ++hf) {
                int row = wm * 32 + mf * 16 + hf * 8 + r0;
                size_t sidx = (size_t)(h * 16 + blockIdx.x) * SEQ + qb + row;
                pmax[sidx] = rmax[mf][hf];
                psum[sidx] = sSum[row * 2] + sSum[row * 2 + 1];
            }
    }

    // split-store S
#pragma unroll
    for (int mf = 0; mf < 2; ++mf)
#pragma unroll
        for (int hf = 0; hf < 2; ++hf) {
            int qrow = qb + wm * 32 + mf * 16 + hf * 8 + r0;
            size_t rbase = ((size_t)h * SEQ + qrow) * SEQ + kb;
#pragma unroll
            for (int nf = 0; nf < 8; ++nf) {
                int col = wn * 64 + nf * 8 + c0;
                float s0 = acc[mf][nf][hf * 2];
                float s1 = acc[mf][nf][hf * 2 + 1];
                __nv_bfloat16 h0 = __float2bfloat16(s0);
                __nv_bfloat16 h1 = __float2bfloat16(s1);
                __nv_bfloat16 l0 = __float2bfloat16(s0 - __bfloat162float(h0));
                __nv_bfloat16 l1 = __float2bfloat16(s1 - __bfloat162float(h1));
                *(__nv_bfloat162*)&Sh[rbase + col] = __nv_bfloat162(h0, h1);
                *(__nv_bfloat162*)&Sl[rbase + col] = __nv_bfloat162(l0, l1);
            }
        }
}

// ===========================================================================
// stats_reduce: fold 16 partials per row into (max, 1/sum)
// ===========================================================================
__global__ __launch_bounds__(256) void stats_reduce(
    const float* __restrict__ pmax, const float* __restrict__ psum,
    float* __restrict__ stats)
{
    int r = blockIdx.x * 256 + threadIdx.x;    // 0 .. NH*SEQ-1
    int h = r >> 11, q = r & 2047;
    float M = -INFINITY;
#pragma unroll
    for (int kt = 0; kt < 16; ++kt)
        M = fmaxf(M, pmax[(size_t)(h * 16 + kt) * SEQ + q]);
    float S = 0.f;
#pragma unroll
    for (int kt = 0; kt < 16; ++kt) {
        size_t i = (size_t)(h * 16 + kt) * SEQ + q;
        S += psum[i] * __expf(pmax[i] - M);
    }
    *(float2*)&stats[(size_t)r * 2] = make_float2(M, 1.0f / S);
}

// ===========================================================================
// attn_pv2: fused softmax-emit + P@V.
// Loads S tiles, converts to P in smem (writes attn fp32 to global once),
// V via ldmatrix.trans from row-major split. ctx out.
// ===========================================================================
#define PA_TILE (128 * 80)                       // 10240
#define PB_TILE (32 * 144)                       // 4608
#define PV_STAGE (2 * PA_TILE + 2 * PB_TILE)     // 29696
#define PV_OFF_ST (2 * PV_STAGE)                 // 59392
#define PV_SMEM (PV_OFF_ST + 1024)               // 60416

__global__ __launch_bounds__(256) void attn_pv2(
    const __nv_bfloat16* __restrict__ Sh, const __nv_bfloat16* __restrict__ Sl,
    const __nv_bfloat16* __restrict__ Vh, const __nv_bfloat16* __restrict__ Vl,
    const float* __restrict__ stats,
    float* __restrict__ attn, float* __restrict__ ctx)
{
    extern __shared__ char smem[];
    uint32_t sb = smem_to_u32(smem);

    const int tid  = threadIdx.x;
    const int lane = tid & 31;
    const int wid  = tid >> 5;
    const int wm   = wid >> 1;
    const int wn   = wid & 1;
    const int h    = blockIdx.y;
    const int bm   = blockIdx.x * 128;

    float* sM = (float*)(smem + PV_OFF_ST);
    float* sI = sM + 128;
    if (tid < 128) {
        float2 st = *(const float2*)&stats[((size_t)h * SEQ + bm + tid) * 2];
        sM[tid] = st.x;
        sI[tid] = st.y;
    }

    float acc[2][4][4];
#pragma unroll
    for (int i = 0; i < 2; ++i)
#pragma unroll
        for (int j = 0; j < 4; ++j)
#pragma unroll
            for (int c = 0; c < 4; ++c) acc[i][j][c] = 0.f;

    auto issue_stage = [&](int it, int s) {
#pragma unroll
        for (int j = 0; j < 6; ++j) {
            int c2 = tid + j * 256;
            uint32_t sm;
            const __nv_bfloat16* g8;
            if (c2 < 1024) {
                int mat = c2 >> 9;
                int idx = c2 & 511;
                int r = idx >> 2, c = idx & 3;
                sm = sb + (uint32_t)(s * PV_STAGE + mat * PA_TILE + r * 80 + c * 16);
                g8 = (mat ? Sl : Sh) + ((size_t)h * SEQ + bm + r) * SEQ + it * 32 + c * 8;
            } else {
                int c2b = c2 - 1024;
                int mat = c2b >> 8;
                int idx = c2b & 255;
                int r = idx >> 3, c = idx & 7;
                sm = sb + (uint32_t)(s * PV_STAGE + 2 * PA_TILE + mat * PB_TILE + r * 144 + c * 16);
                g8 = (mat ? Vl : Vh) + (size_t)(it * 32 + r) * DM + h * DKH + c * 8;
            }
            CP_ASYNC16(sm, g8);
        }
        CP_COMMIT();
    };

    issue_stage(0, 0);

    for (int it = 0; it < SEQ / 32; ++it) {
        const int s = it & 1;
        if (it + 1 < SEQ / 32) { issue_stage(it + 1, s ^ 1); CP_WAIT1(); }
        else                   { CP_WAIT0(); }
        __syncthreads();

        // ---- convert S -> P in place (and emit attn tile) ----
        {
            char* pa = smem + s * PV_STAGE;
            char* pl = pa + PA_TILE;
#pragma unroll
            for (int j = 0; j < 2; ++j) {
                int idx = tid + j * 256;       // 0..511
                int r = idx >> 2, c = idx & 3;
                uint4 uh = *(uint4*)(pa + r * 80 + c * 16);
                uint4 ul = *(uint4*)(pl + r * 80 + c * 16);
                __nv_bfloat162* hb = (__nv_bfloat162*)&uh;
                __nv_bfloat162* lb = (__nv_bfloat162*)&ul;
                float m = sM[r], inv = sI[r];
                float p[8];
#pragma unroll
                for (int e = 0; e < 4; ++e) {
                    float sx = __bfloat162float(hb[e].x) + __bfloat162float(lb[e].x);
                    float sy = __bfloat162float(hb[e].y) + __bfloat162float(lb[e].y);
                    p[2 * e]     = __expf(sx - m) * inv;
                    p[2 * e + 1] = __expf(sy - m) * inv;
                }
                uint4 oh, ol;
                __nv_bfloat162* ohb = (__nv_bfloat162*)&oh;
                __nv_bfloat162* olb = (__nv_bfloat162*)&ol;
#pragma unroll
                for (int e = 0; e < 4; ++e) {
                    __nv_bfloat16 h0 = __float2bfloat16(p[2 * e]);
                    __nv_bfloat16 h1 = __float2bfloat16(p[2 * e + 1]);
                    __nv_bfloat16 l0 = __float2bfloat16(p[2 * e]     - __bfloat162float(h0));
                    __nv_bfloat16 l1 = __float2bfloat16(p[2 * e + 1] - __bfloat162float(h1));
                    ohb[e] = __nv_bfloat162(h0, h1);
                    olb[e] = __nv_bfloat162(l0, l1);
                }
                *(uint4*)(pa + r * 80 + c * 16) = oh;
                *(uint4*)(pl + r * 80 + c * 16) = ol;
                float* ga = attn + ((size_t)h * SEQ + bm + r) * SEQ + it * 32 + c * 8;
                *(float4*)ga       = make_float4(p[0], p[1], p[2], p[3]);
                *(float4*)(ga + 4) = make_float4(p[4], p[5], p[6], p[7]);
            }
        }
        __syncthreads();

        // ---- mma: P (row-major) x V (trans-ldmatrix from row-major) ----
        const uint32_t aHb = sb + s * PV_STAGE;
        const uint32_t aLb = aHb + PA_TILE;
        const uint32_t vHb = aHb + 2 * PA_TILE;
        const uint32_t vLb = vHb + PB_TILE;

#pragma unroll
        for (int ks = 0; ks < 2; ++ks) {
            uint32_t aoff = (uint32_t)((wm * 32 + (lane & 15)) * 80 + ks * 32 + (lane >> 4) * 16);
            uint32_t ah0[4], ah1[4], al0[4], al1[4];
            LDSM_X4(ah0[0], ah0[1], ah0[2], ah0[3], aHb + aoff);
            LDSM_X4(ah1[0], ah1[1], ah1[2], ah1[3], aHb + aoff + 16 * 80);
            LDSM_X4(al0[0], al0[1], al0[2], al0[3], aLb + aoff);
            LDSM_X4(al1[0], al1[1], al1[2], al1[3], aLb + aoff + 16 * 80);

            const int vrow = ks * 16 + ((lane >> 3) & 1) * 8 + (lane & 7);
            uint32_t bh[2][4], bl[2][4];
#pragma unroll
            for (int p = 0; p < 2; ++p) {
                int vcol = wn * 32 + p * 16 + ((lane >> 4) & 1) * 8;
                uint32_t voff = (uint32_t)(vrow * 144 + vcol * 2);
                LDSM_X4T(bh[p][0], bh[p][1], bh[p][2], bh[p][3], vHb + voff);
                LDSM_X4T(bl[p][0], bl[p][1], bl[p][2], bl[p][3], vLb + voff);
            }
#pragma unroll
            for (int mf = 0; mf < 2; ++mf) {
                const uint32_t* Ah_ = mf ? ah1 : ah0;
                const uint32_t* Al_ = mf ? al1 : al0;
#pragma unroll
                for (int p = 0; p < 2; ++p) {
                    MMA16816(acc[mf][2 * p],     Ah_, bh[p][0], bh[p][1]);
                    MMA16816(acc[mf][2 * p + 1], Ah_, bh[p][2], bh[p][3]);
                    MMA16816(acc[mf][2 * p],     Ah_, bl[p][0], bl[p][1]);
                    MMA16816(acc[mf][2 * p + 1], Ah_, bl[p][2], bl[p][3]);
                    MMA16816(acc[mf][2 * p],     Al_, bh[p][0], bh[p][1]);
                    MMA16816(acc[mf][2 * p + 1], Al_, bh[p][2], bh[p][3]);
                }
            }
        }
        __syncthreads();
    }

    const int l4 = lane >> 2;
    const int l2 = (lane & 3) * 2;
#pragma unroll
    for (int mf = 0; mf < 2; ++mf) {
        int q = bm + wm * 32 + mf * 16 + l4;
#pragma unroll
        for (int nf = 0; nf < 4; ++nf) {
            int col = h * DKH + wn * 32 + nf * 8 + l2;
            float2 v0 = { acc[mf][nf][0], acc[mf][nf][1] };
            float2 v1 = { acc[mf][nf][2], acc[mf][nf][3] };
            *(float2*)&ctx[(size_t)q * DM + col]       = v0;
            *(float2*)&ctx[(size_t)(q + 8) * DM + col] = v1;
        }
    }
}

// ===========================================================================
extern "C" void kernel_launch(void* const* d_in, const int* in_sizes, int n_in,
                              void* d_out, int out_size)
{
    const float* q    = (const float*)d_in[0];
    const float* k    = (const float*)d_in[1];
    const float* v    = (const float*)d_in[2];
    const int*   mask = (const int*)  d_in[3];
    const float* Wq   = (const float*)d_in[4];
    const float* bq   = (const float*)d_in[5];
    const float* Wk   = (const float*)d_in[6];
    const float* bk   = (const float*)d_in[7];
    const float* Wv   = (const float*)d_in[8];
    const float* bv   = (const float*)d_in[9];
    const float* Wo   = (const float*)d_in[10];
    const float* bo   = (const float*)d_in[11];

    float *Qp, *Kp, *Vp, *Cp, *Ap, *Op, *pmaxp, *psump, *statsp;
    cudaGetSymbolAddress((void**)&Qp, g_Q);
    cudaGetSymbolAddress((void**)&Kp, g_K);
    cudaGetSymbolAddress((void**)&Vp, g_V);
    cudaGetSymbolAddress((void**)&Cp, g_CTX);
    cudaGetSymbolAddress((void**)&Ap, g_ATTN);
    cudaGetSymbolAddress((void**)&Op, g_OUT);
    cudaGetSymbolAddress((void**)&pmaxp, g_pmax);
    cudaGetSymbolAddress((void**)&psump, g_psum);
    cudaGetSymbolAddress((void**)&statsp, g_stats);

    __nv_bfloat16 *qh, *ql, *kh, *kl, *vh, *vl, *ch, *cl, *Shp, *Slp;
    __nv_bfloat16 *Wqh, *Wql, *Wkh, *Wkl, *Wvh, *Wvl, *Woh, *Wol;
    cudaGetSymbolAddress((void**)&qh, g_qh);   cudaGetSymbolAddress((void**)&ql, g_ql);
    cudaGetSymbolAddress((void**)&kh, g_kh);   cudaGetSymbolAddress((void**)&kl, g_kl);
    cudaGetSymbolAddress((void**)&vh, g_vh);   cudaGetSymbolAddress((void**)&vl, g_vl);
    cudaGetSymbolAddress((void**)&ch, g_ch);   cudaGetSymbolAddress((void**)&cl, g_cl);
    cudaGetSymbolAddress((void**)&Shp, g_Sh);  cudaGetSymbolAddress((void**)&Slp, g_Sl);
    cudaGetSymbolAddress((void**)&Wqh, g_Wqh); cudaGetSymbolAddress((void**)&Wql, g_Wql);
    cudaGetSymbolAddress((void**)&Wkh, g_Wkh); cudaGetSymbolAddress((void**)&Wkl, g_Wkl);
    cudaGetSymbolAddress((void**)&Wvh, g_Wvh); cudaGetSymbolAddress((void**)&Wvl, g_Wvl);
    cudaGetSymbolAddress((void**)&Woh, g_Woh); cudaGetSymbolAddress((void**)&Wol, g_Wol);

    const size_t OUT_ELEMS  = (size_t)SEQ * DM;
    const size_t ATTN_ELEMS = (size_t)NH * SEQ * SEQ;

    float* outp = (float*)d_out;
    float* attnp;
    if ((size_t)out_size >= OUT_ELEMS + ATTN_ELEMS) {
        attnp = outp + OUT_ELEMS;
    } else if ((size_t)out_size == ATTN_ELEMS) {
        attnp = (float*)d_out;
        outp  = Op;
    } else {
        attnp = Ap;
    }

    cudaFuncSetAttribute(gemm_mma,
                         cudaFuncAttributeMaxDynamicSharedMemorySize, GEMM_SMEM);
    cudaFuncSetAttribute(attn_sgemm,
                         cudaFuncAttributeMaxDynamicSharedMemorySize, SG_SMEM);
    cudaFuncSetAttribute(attn_pv2,
                         cudaFuncAttributeMaxDynamicSharedMemorySize, PV_SMEM);

    // 1) split inputs + weights
    {
        PrepBatch pb;
        pb.src[0] = q;  pb.hi[0] = qh;  pb.lo[0] = ql;  pb.n4[0] = SEQ * DM / 4;
        pb.src[1] = k;  pb.hi[1] = kh;  pb.lo[1] = kl;  pb.n4[1] = SEQ * DM / 4;
        pb.src[2] = v;  pb.hi[2] = vh;  pb.lo[2] = vl;  pb.n4[2] = SEQ * DM / 4;
        pb.src[3] = Wq; pb.hi[3] = Wqh; pb.lo[3] = Wql; pb.n4[3] = DM * DM / 4;
        pb.src[4] = Wk; pb.hi[4] = Wkh; pb.lo[4] = Wkl; pb.n4[4] = DM * DM / 4;
        pb.src[5] = Wv; pb.hi[5] = Wvh; pb.lo[5] = Wvl; pb.n4[5] = DM * DM / 4;
        pb.src[6] = Wo; pb.hi[6] = Woh; pb.lo[6] = Wol; pb.n4[6] = DM * DM / 4;
        pb.src[7] = q;  pb.hi[7] = qh;  pb.lo[7] = ql;  pb.n4[7] = 0;
        dim3 pg((SEQ * DM / 4 + 255) / 256, 1, 7);
        split_prep<<<pg, 256>>>(pb);
    }

    // 2) Q/K/V projections
    {
        GemmBatch gb;
        gb.g[0] = { qh, ql, Wqh, Wql, bq, Qp };
        gb.g[1] = { kh, kl, Wkh, Wkl, bk, Kp };
        gb.g[2] = { vh, vl, Wvh, Wvl, bv, Vp };
        gemm_mma<<<dim3(DM / 128, SEQ / 128, 3), 256, GEMM_SMEM>>>(gb);
    }

    // 3) split projected Q, K, V (overwrites input splits; safe)
    {
        PrepBatch pb;
        pb.src[0] = Qp; pb.hi[0] = qh; pb.lo[0] = ql; pb.n4[0] = SEQ * DM / 4;
        pb.src[1] = Kp; pb.hi[1] = kh; pb.lo[1] = kl; pb.n4[1] = SEQ * DM / 4;
        pb.src[2] = Vp; pb.hi[2] = vh; pb.lo[2] = vl; pb.n4[2] = SEQ * DM / 4;
        for (int i = 3; i < 8; ++i) { pb.src[i] = Qp; pb.hi[i] = qh; pb.lo[i] = ql; pb.n4[i] = 0; }
        dim3 pg((SEQ * DM / 4 + 255) / 256, 1, 3);
        split_prep<<<pg, 256>>>(pb);
    }

    // 4) scores GEMM -> split S + partial stats
    attn_sgemm<<<dim3(SEQ / 128, SEQ / 128, NH), 256, SG_SMEM>>>(
        qh, ql, kh, kl, mask, Shp, Slp, pmaxp, psump);

    // 5) stats reduction
    stats_reduce<<<(NH * SEQ) / 256, 256>>>(pmaxp, psump, statsp);

    // 6) fused softmax-emit + P@V
    attn_pv2<<<dim3(SEQ / 128, NH), 256, PV_SMEM>>>(
        Shp, Slp, vh, vl, statsp, attnp, Cp);

    // 7) split ctx + output projection
    {
        PrepBatch pb;
        pb.src[0] = Cp; pb.hi[0] = ch; pb.lo[0] = cl; pb.n4[0] = SEQ * DM / 4;
        for (int i = 1; i < 8; ++i) { pb.src[i] = Cp; pb.hi[i] = ch; pb.lo[i] = cl; pb.n4[i] = 0; }
        dim3 pg((SEQ * DM / 4 + 255) / 256, 1, 1);
        split_prep<<<pg, 256>>>(pb);

        GemmBatch gb;
        gb.g[0] = { ch, cl, Woh, Wol, bo, outp };
        gb.g[1] = gb.g[0];
        gb.g[2] = gb.g[0];
        gemm_mma<<<dim3(DM / 128, SEQ / 128, 1), 256, GEMM_SMEM>>>(gb);
    }
}

// round 7
// speedup vs baseline: 3.7601x; 1.0037x over previous
#include <cuda_runtime.h>
#include <cuda_bf16.h>
#include <math.h>
#include <stdint.h>

// Problem constants
#define SEQ 2048
#define DM  1024
#define NH  16
#define DKH 64

// ===========================================================================
// Portable PTX helpers (base compute_103 target)
// ===========================================================================
__device__ __forceinline__ uint32_t smem_to_u32(const void* smem_ptr) {
    uint32_t addr;
    asm("{ .reg .u64 tmp; cvta.to.shared.u64 tmp, %1; cvt.u32.u64 %0, tmp; }"
        : "=r"(addr) : "l"(smem_ptr));
    return addr;
}

#define LDSM_X4(r0, r1, r2, r3, addr) \
    asm volatile("ldmatrix.sync.aligned.m8n8.x4.shared.b16 {%0,%1,%2,%3}, [%4];" \
        : "=r"(r0), "=r"(r1), "=r"(r2), "=r"(r3) : "r"(addr))

#define LDSM_X4T(r0, r1, r2, r3, addr) \
    asm volatile("ldmatrix.sync.aligned.m8n8.x4.trans.shared.b16 {%0,%1,%2,%3}, [%4];" \
        : "=r"(r0), "=r"(r1), "=r"(r2), "=r"(r3) : "r"(addr))

#define MMA16816(c, a, b0, b1) \
    asm volatile("mma.sync.aligned.m16n8k16.row.col.f32.bf16.bf16.f32 " \
        "{%0,%1,%2,%3},{%4,%5,%6,%7},{%8,%9},{%0,%1,%2,%3};" \
        : "+f"((c)[0]), "+f"((c)[1]), "+f"((c)[2]), "+f"((c)[3]) \
        : "r"((a)[0]), "r"((a)[1]), "r"((a)[2]), "r"((a)[3]), "r"(b0), "r"(b1))

#define CP_ASYNC16(smaddr, gptr) \
    asm volatile("cp.async.cg.shared.global [%0], [%1], 16;" \
        :: "r"(smaddr), "l"(gptr))
#define CP_COMMIT() asm volatile("cp.async.commit_group;" ::: "memory")
#define CP_WAIT0()  asm volatile("cp.async.wait_group 0;" ::: "memory")
#define CP_WAIT1()  asm volatile("cp.async.wait_group 1;" ::: "memory")

__device__ __forceinline__ void split2(float x, __nv_bfloat16& h, __nv_bfloat16& l) {
    h = __float2bfloat16(x);
    l = __float2bfloat16(x - __bfloat162float(h));
}

// ===========================================================================
// Scratch (device globals)
// ===========================================================================
__device__ float g_Q[SEQ * DM];      // reused as bf16 split of projected Q (hi|lo)
__device__ float g_K[SEQ * DM];      // reused as bf16 split of projected K
__device__ float g_V[SEQ * DM];      // reused as bf16 split of projected V
__device__ float g_OUT[SEQ * DM];
__device__ float g_ATTN[(size_t)NH * SEQ * SEQ];

__device__ __nv_bfloat16 g_qh[SEQ * DM],  g_ql[SEQ * DM];
__device__ __nv_bfloat16 g_kh[SEQ * DM],  g_kl[SEQ * DM];
__device__ __nv_bfloat16 g_vh[SEQ * DM],  g_vl[SEQ * DM];
__device__ __nv_bfloat16 g_ch[SEQ * DM],  g_cl[SEQ * DM];
__device__ __nv_bfloat16 g_Wqh[DM * DM], g_Wql[DM * DM];
__device__ __nv_bfloat16 g_Wkh[DM * DM], g_Wkl[DM * DM];
__device__ __nv_bfloat16 g_Wvh[DM * DM], g_Wvl[DM * DM];
__device__ __nv_bfloat16 g_Woh[DM * DM], g_Wol[DM * DM];

__device__ __nv_bfloat16 g_Sh[(size_t)NH * SEQ * SEQ];
__device__ __nv_bfloat16 g_Sl[(size_t)NH * SEQ * SEQ];

__device__ float g_pmax[NH * 16 * SEQ];
__device__ float g_psum[NH * 16 * SEQ];

// ===========================================================================
// Split-precision prep: x -> (bf16 hi, bf16 lo)
// ===========================================================================
struct PrepBatch {
    const float* src[8];
    __nv_bfloat16* hi[8];
    __nv_bfloat16* lo[8];
    int n4[8];
};

__global__ __launch_bounds__(256) void split_prep(PrepBatch pb)
{
    int z = blockIdx.z;
    int i = blockIdx.x * 256 + threadIdx.x;
    if (i >= pb.n4[z]) return;
    float4 v = ((const float4*)pb.src[z])[i];
    __nv_bfloat16 h0, h1, h2, h3, l0, l1, l2, l3;
    split2(v.x, h0, l0); split2(v.y, h1, l1);
    split2(v.z, h2, l2); split2(v.w, h3, l3);
    __nv_bfloat162* hp = (__nv_bfloat162*)pb.hi[z];
    __nv_bfloat162* lp = (__nv_bfloat162*)pb.lo[z];
    hp[2 * i]     = __nv_bfloat162(h0, h1);
    hp[2 * i + 1] = __nv_bfloat162(h2, h3);
    lp[2 * i]     = __nv_bfloat162(l0, l1);
    lp[2 * i + 1] = __nv_bfloat162(l2, l3);
}

// ===========================================================================
// mma.sync split-bf16 GEMM: C = A @ W^T + bias.
// Output either fp32 (C) or bf16 hi/lo split (Ch/Cl).
// ===========================================================================
#define GP 40
#define TILE_B (128 * GP * 2)
#define STAGE_B (4 * TILE_B)
#define GEMM_SMEM (2 * STAGE_B)

struct GemmPtrs {
    const __nv_bfloat16 *Ah, *Al, *Bh, *Bl;
    const float* bias;
    float* C;                 // fp32 out (or null)
    __nv_bfloat16 *Ch, *Cl;   // split out (or null)
};
struct GemmBatch { GemmPtrs g[3]; };

__global__ __launch_bounds__(256, 2) void gemm_mma(GemmBatch batch)
{
    GemmPtrs gp = batch.g[blockIdx.z];
    extern __shared__ char smem[];
    uint32_t sb = smem_to_u32(smem);

    const int tid  = threadIdx.x;
    const int lane = tid & 31;
    const int wid  = tid >> 5;
    const int wm   = wid >> 1;
    const int wn   = wid & 1;
    const int bm   = blockIdx.y * 128;
    const int bn   = blockIdx.x * 128;

    const __nv_bfloat16* tp[4] = { gp.Ah, gp.Al, gp.Bh, gp.Bl };

    float acc[2][8][4];
#pragma unroll
    for (int i = 0; i < 2; ++i)
#pragma unroll
        for (int j = 0; j < 8; ++j)
#pragma unroll
            for (int c = 0; c < 4; ++c) acc[i][j][c] = 0.f;

    auto issue_stage = [&](int it, int s) {
#pragma unroll
        for (int j = 0; j < 8; ++j) {
            int c2  = tid + j * 256;
            int tt  = c2 >> 9;
            int idx = c2 & 511;
            int r   = idx >> 2;
            int c   = idx & 3;
            uint32_t sm = sb + (uint32_t)(s * STAGE_B + tt * TILE_B + r * 80 + c * 16);
            int grow = ((tt < 2) ? bm : bn) + r;
            const __nv_bfloat16* g8 = tp[tt] + (size_t)grow * DM + it * 32 + c * 8;
            CP_ASYNC16(sm, g8);
        }
        CP_COMMIT();
    };

    issue_stage(0, 0);

    for (int it = 0; it < DM / 32; ++it) {
        const int s = it & 1;
        if (it + 1 < DM / 32) { issue_stage(it + 1, (it + 1) & 1); CP_WAIT1(); }
        else                  { CP_WAIT0(); }
        __syncthreads();

        const uint32_t base = sb + s * STAGE_B;
        const uint32_t aH = base;
        const uint32_t aL = base + TILE_B;
        const uint32_t bH = base + 2 * TILE_B;
        const uint32_t bL = base + 3 * TILE_B;

#pragma unroll
        for (int ks = 0; ks < 2; ++ks) {
            const uint32_t aoff = (uint32_t)((wm * 32 + (lane & 15)) * 80 + ks * 32 + (lane >> 4) * 16);
            uint32_t ah0[4], ah1[4], al0[4], al1[4];
            LDSM_X4(ah0[0], ah0[1], ah0[2], ah0[3], aH + aoff);
            LDSM_X4(ah1[0], ah1[1], ah1[2], ah1[3], aH + aoff + 16 * 80);
            LDSM_X4(al0[0], al0[1], al0[2], al0[3], aL + aoff);
            LDSM_X4(al1[0], al1[1], al1[2], al1[3], aL + aoff + 16 * 80);

            const int brow = (lane & 7) + ((lane >> 4) << 3);
            const uint32_t bko = (uint32_t)(ks * 32 + ((lane >> 3) & 1) * 16);
            uint32_t bh[4][4], bl[4][4];
#pragma unroll
            for (int p = 0; p < 4; ++p) {
                uint32_t boff = (uint32_t)((wn * 64 + p * 16 + brow) * 80) + bko;
                LDSM_X4(bh[p][0], bh[p][1], bh[p][2], bh[p][3], bH + boff);
                LDSM_X4(bl[p][0], bl[p][1], bl[p][2], bl[p][3], bL + boff);
            }

#pragma unroll
            for (int mf = 0; mf < 2; ++mf) {
                const uint32_t* Ah_ = mf ? ah1 : ah0;
                const uint32_t* Al_ = mf ? al1 : al0;
#pragma unroll
                for (int p = 0; p < 4; ++p) {
                    MMA16816(acc[mf][2 * p],     Ah_, bh[p][0], bh[p][1]);
                    MMA16816(acc[mf][2 * p + 1], Ah_, bh[p][2], bh[p][3]);
                    MMA16816(acc[mf][2 * p],     Ah_, bl[p][0], bl[p][1]);
                    MMA16816(acc[mf][2 * p + 1], Ah_, bl[p][2], bl[p][3]);
                    MMA16816(acc[mf][2 * p],     Al_, bh[p][0], bh[p][1]);
                    MMA16816(acc[mf][2 * p + 1], Al_, bh[p][2], bh[p][3]);
                }
            }
        }
        __syncthreads();
    }

    const int l4 = lane >> 2;
    const int l2 = (lane & 3) * 2;
#pragma unroll
    for (int mf = 0; mf < 2; ++mf) {
        int r0 = bm + wm * 32 + mf * 16 + l4;
#pragma unroll
        for (int nf = 0; nf < 8; ++nf) {
            int col = bn + wn * 64 + nf * 8 + l2;
            float2 bb = *(const float2*)&gp.bias[col];
            float v00 = acc[mf][nf][0] + bb.x, v01 = acc[mf][nf][1] + bb.y;
            float v10 = acc[mf][nf][2] + bb.x, v11 = acc[mf][nf][3] + bb.y;
            if (gp.Ch) {
                __nv_bfloat16 h0, h1, l0h, l1h;
                split2(v00, h0, l0h); split2(v01, h1, l1h);
                *(__nv_bfloat162*)&gp.Ch[(size_t)r0 * DM + col] = __nv_bfloat162(h0, h1);
                *(__nv_bfloat162*)&gp.Cl[(size_t)r0 * DM + col] = __nv_bfloat162(l0h, l1h);
                split2(v10, h0, l0h); split2(v11, h1, l1h);
                *(__nv_bfloat162*)&gp.Ch[(size_t)(r0 + 8) * DM + col] = __nv_bfloat162(h0, h1);
                *(__nv_bfloat162*)&gp.Cl[(size_t)(r0 + 8) * DM + col] = __nv_bfloat162(l0h, l1h);
            } else {
                *(float2*)&gp.C[(size_t)r0 * DM + col]       = make_float2(v00, v01);
                *(float2*)&gp.C[(size_t)(r0 + 8) * DM + col] = make_float2(v10, v11);
            }
        }
    }
}

// ===========================================================================
// attn_sgemm: S split + partial stats. Term-major with 2 cp.async groups.
// grid (16 ktiles, 16 qtiles, 16 heads), 256 threads.
// ===========================================================================
#define SG_PITCH 144
#define SG_TILE (128 * SG_PITCH)
#define SG_OFF_MASK (4 * SG_TILE)
#define SG_OFF_MAX  (SG_OFF_MASK + 512)
#define SG_OFF_SUM  (SG_OFF_MAX + 1024)
#define SG_SMEM     (SG_OFF_SUM + 1024)

__global__ __launch_bounds__(256) void attn_sgemm(
    const __nv_bfloat16* __restrict__ Qh, const __nv_bfloat16* __restrict__ Ql,
    const __nv_bfloat16* __restrict__ Kh, const __nv_bfloat16* __restrict__ Kl,
    const int* __restrict__ mask,
    __nv_bfloat16* __restrict__ Sh, __nv_bfloat16* __restrict__ Sl,
    float* __restrict__ pmax, float* __restrict__ psum)
{
    extern __shared__ char smem[];
    uint32_t sb = smem_to_u32(smem);
    const int tid = threadIdx.x;
    const int lane = tid & 31;
    const int wid = tid >> 5;
    const int wm = wid >> 1;
    const int wn = wid & 1;
    const int h  = blockIdx.z;
    const int kb = blockIdx.x * 128;
    const int qb = blockIdx.y * 128;

    auto load_tile = [&](int tt, const __nv_bfloat16* src, int grow0) {
#pragma unroll
        for (int j = 0; j < 4; ++j) {
            int idx = tid + j * 256;
            int r = idx >> 3, c = idx & 7;
            uint32_t sm = sb + (uint32_t)(tt * SG_TILE + r * SG_PITCH + c * 16);
            CP_ASYNC16(sm, src + (size_t)(grow0 + r) * DM + h * DKH + c * 8);
        }
    };

    // group A: hi tiles; group B: lo tiles
    load_tile(0, Qh, qb);
    load_tile(2, Kh, kb);
    CP_COMMIT();
    load_tile(1, Ql, qb);
    load_tile(3, Kl, kb);
    CP_COMMIT();
    int* sMask = (int*)(smem + SG_OFF_MASK);
    if (tid < 128) sMask[tid] = mask[kb + tid];

    float acc[2][8][4];
#pragma unroll
    for (int i = 0; i < 2; ++i)
#pragma unroll
        for (int j = 0; j < 8; ++j)
#pragma unroll
            for (int c = 0; c < 4; ++c) acc[i][j][c] = 0.f;

    const uint32_t aH = sb, aL = sb + SG_TILE, bH = sb + 2 * SG_TILE, bL = sb + 3 * SG_TILE;
    const int brow = (lane & 7) + ((lane >> 4) << 3);

    CP_WAIT1();
    __syncthreads();

    // term 1: Ah x Bh (overlaps group-B loads)
#pragma unroll
    for (int ks = 0; ks < 4; ++ks) {
        uint32_t aoff = (uint32_t)((wm * 32 + (lane & 15)) * SG_PITCH + ks * 32 + (lane >> 4) * 16);
        uint32_t ah0[4], ah1[4];
        LDSM_X4(ah0[0], ah0[1], ah0[2], ah0[3], aH + aoff);
        LDSM_X4(ah1[0], ah1[1], ah1[2], ah1[3], aH + aoff + 16 * SG_PITCH);
        uint32_t bko = (uint32_t)(ks * 32 + ((lane >> 3) & 1) * 16);
#pragma unroll
        for (int p = 0; p < 4; ++p) {
            uint32_t boff = (uint32_t)((wn * 64 + p * 16 + brow) * SG_PITCH) + bko;
            uint32_t b0, b1, b2, b3;
            LDSM_X4(b0, b1, b2, b3, bH + boff);
            MMA16816(acc[0][2 * p],     ah0, b0, b1);
            MMA16816(acc[0][2 * p + 1], ah0, b2, b3);
            MMA16816(acc[1][2 * p],     ah1, b0, b1);
            MMA16816(acc[1][2 * p + 1], ah1, b2, b3);
        }
    }

    CP_WAIT0();
    __syncthreads();

    // terms 2+3: Ah x Bl, Al x Bh
#pragma unroll
    for (int ks = 0; ks < 4; ++ks) {
        uint32_t aoff = (uint32_t)((wm * 32 + (lane & 15)) * SG_PITCH + ks * 32 + (lane >> 4) * 16);
        uint32_t ah0[4], ah1[4], al0[4], al1[4];
        LDSM_X4(ah0[0], ah0[1], ah0[2], ah0[3], aH + aoff);
        LDSM_X4(ah1[0], ah1[1], ah1[2], ah1[3], aH + aoff + 16 * SG_PITCH);
        LDSM_X4(al0[0], al0[1], al0[2], al0[3], aL + aoff);
        LDSM_X4(al1[0], al1[1], al1[2], al1[3], aL + aoff + 16 * SG_PITCH);
        uint32_t bko = (uint32_t)(ks * 32 + ((lane >> 3) & 1) * 16);
#pragma unroll
        for (int p = 0; p < 4; ++p) {
            uint32_t boff = (uint32_t)((wn * 64 + p * 16 + brow) * SG_PITCH) + bko;
            uint32_t bh0, bh1, bh2, bh3, bl0, bl1, bl2, bl3;
            LDSM_X4(bh0, bh1, bh2, bh3, bH + boff);
            LDSM_X4(bl0, bl1, bl2, bl3, bL + boff);
            MMA16816(acc[0][2 * p],     ah0, bl0, bl1);
            MMA16816(acc[0][2 * p + 1], ah0, bl2, bl3);
            MMA16816(acc[1][2 * p],     ah1, bl0, bl1);
            MMA16816(acc[1][2 * p + 1], ah1, bl2, bl3);
            MMA16816(acc[0][2 * p],     al0, bh0, bh1);
            MMA16816(acc[0][2 * p + 1], al0, bh2, bh3);
            MMA16816(acc[1][2 * p],     al1, bh0, bh1);
            MMA16816(acc[1][2 * p + 1], al1, bh2, bh3);
        }
    }

    // ---- epilogue: scale+mask, partial softmax stats, split-store S ----
    const int c0 = (lane & 3) * 2;
    const int r0 = lane >> 2;
#pragma unroll
    for (int mf = 0; mf < 2; ++mf)
#pragma unroll
        for (int nf = 0; nf < 8; ++nf) {
            int col = wn * 64 + nf * 8 + c0;
            bool k0 = sMask[col] != 0, k1 = sMask[col + 1] != 0;
            acc[mf][nf][0] = k0 ? acc[mf][nf][0] * 0.125f : -1e9f;
            acc[mf][nf][1] = k1 ? acc[mf][nf][1] * 0.125f : -1e9f;
            acc[mf][nf][2] = k0 ? acc[mf][nf][2] * 0.125f : -1e9f;
            acc[mf][nf][3] = k1 ? acc[mf][nf][3] * 0.125f : -1e9f;
        }

    float* sMax = (float*)(smem + SG_OFF_MAX);
    float* sSum = (float*)(smem + SG_OFF_SUM);
    float rmax[2][2];
#pragma unroll
    for (int mf = 0; mf < 2; ++mf)
#pragma unroll
        for (int hf = 0; hf < 2; ++hf) {
            float m = -INFINITY;
#pragma unroll
            for (int nf = 0; nf < 8; ++nf) {
                m = fmaxf(m, acc[mf][nf][hf * 2]);
                m = fmaxf(m, acc[mf][nf][hf * 2 + 1]);
            }
            m = fmaxf(m, __shfl_xor_sync(0xffffffffu, m, 1));
            m = fmaxf(m, __shfl_xor_sync(0xffffffffu, m, 2));
            rmax[mf][hf] = m;
            if ((lane & 3) == 0) sMax[(wm * 32 + mf * 16 + hf * 8 + r0) * 2 + wn] = m;
        }
    __syncthreads();
#pragma unroll
    for (int mf = 0; mf < 2; ++mf)
#pragma unroll
        for (int hf = 0; hf < 2; ++hf) {
            int row = wm * 32 + mf * 16 + hf * 8 + r0;
            float M = fmaxf(sMax[row * 2], sMax[row * 2 + 1]);
            rmax[mf][hf] = M;
            float s = 0.f;
#pragma unroll
            for (int nf = 0; nf < 8; ++nf) {
                s += __expf(acc[mf][nf][hf * 2] - M);
                s += __expf(acc[mf][nf][hf * 2 + 1] - M);
            }
            s += __shfl_xor_sync(0xffffffffu, s, 1);
            s += __shfl_xor_sync(0xffffffffu, s, 2);
            if ((lane & 3) == 0) sSum[row * 2 + wn] = s;
        }
    __syncthreads();
    if (wn == 0 && (lane & 3) == 0) {
#pragma unroll
        for (int mf = 0; mf < 2; ++mf)
#pragma unroll
            for (int hf = 0; hf < 2; ++hf) {
                int row = wm * 32 + mf * 16 + hf * 8 + r0;
                size_t sidx = (size_t)(h * 16 + blockIdx.x) * SEQ + qb + row;
                pmax[sidx] = rmax[mf][hf];
                psum[sidx] = sSum[row * 2] + sSum[row * 2 + 1];
            }
    }

#pragma unroll
    for (int mf = 0; mf < 2; ++mf)
#pragma unroll
        for (int hf = 0; hf < 2; ++hf) {
            int qrow = qb + wm * 32 + mf * 16 + hf * 8 + r0;
            size_t rbase = ((size_t)h * SEQ + qrow) * SEQ + kb;
#pragma unroll
            for (int nf = 0; nf < 8; ++nf) {
                int col = wn * 64 + nf * 8 + c0;
                __nv_bfloat16 h0, h1, l0, l1;
                split2(acc[mf][nf][hf * 2],     h0, l0);
                split2(acc[mf][nf][hf * 2 + 1], h1, l1);
                *(__nv_bfloat162*)&Sh[rbase + col] = __nv_bfloat162(h0, h1);
                *(__nv_bfloat162*)&Sl[rbase + col] = __nv_bfloat162(l0, l1);
            }
        }
}

// ===========================================================================
// attn_pv2: inline stats + fused softmax-emit + P@V; split ctx out.
// ===========================================================================
#define PA_TILE (128 * 80)
#define PB_TILE (32 * 144)
#define PV_STAGE (2 * PA_TILE + 2 * PB_TILE)
#define PV_OFF_ST (2 * PV_STAGE)
#define PV_SMEM (PV_OFF_ST + 1024)

__global__ __launch_bounds__(256, 2) void attn_pv2(
    const __nv_bfloat16* __restrict__ Sh, const __nv_bfloat16* __restrict__ Sl,
    const __nv_bfloat16* __restrict__ Vh, const __nv_bfloat16* __restrict__ Vl,
    const float* __restrict__ pmax, const float* __restrict__ psum,
    float* __restrict__ attn,
    __nv_bfloat16* __restrict__ Ch, __nv_bfloat16* __restrict__ Cl)
{
    extern __shared__ char smem[];
    uint32_t sb = smem_to_u32(smem);

    const int tid  = threadIdx.x;
    const int lane = tid & 31;
    const int wid  = tid >> 5;
    const int wm   = wid >> 1;
    const int wn   = wid & 1;
    const int h    = blockIdx.y;
    const int bm   = blockIdx.x * 128;

    float acc[2][4][4];
#pragma unroll
    for (int i = 0; i < 2; ++i)
#pragma unroll
        for (int j = 0; j < 4; ++j)
#pragma unroll
            for (int c = 0; c < 4; ++c) acc[i][j][c] = 0.f;

    auto issue_stage = [&](int it, int s) {
#pragma unroll
        for (int j = 0; j < 6; ++j) {
            int c2 = tid + j * 256;
            uint32_t sm;
            const __nv_bfloat16* g8;
            if (c2 < 1024) {
                int mat = c2 >> 9;
                int idx = c2 & 511;
                int r = idx >> 2, c = idx & 3;
                sm = sb + (uint32_t)(s * PV_STAGE + mat * PA_TILE + r * 80 + c * 16);
                g8 = (mat ? Sl : Sh) + ((size_t)h * SEQ + bm + r) * SEQ + it * 32 + c * 8;
            } else {
                int c2b = c2 - 1024;
                int mat = c2b >> 8;
                int idx = c2b & 255;
                int r = idx >> 3, c = idx & 7;
                sm = sb + (uint32_t)(s * PV_STAGE + 2 * PA_TILE + mat * PB_TILE + r * 144 + c * 16);
                g8 = (mat ? Vl : Vh) + (size_t)(it * 32 + r) * DM + h * DKH + c * 8;
            }
            CP_ASYNC16(sm, g8);
        }
        CP_COMMIT();
    };

    issue_stage(0, 0);

    // inline stats: fold 16 partial (max,sum) per row
    float* sM = (float*)(smem + PV_OFF_ST);
    float* sI = sM + 128;
    if (tid < 128) {
        int qrow = bm + tid;
        float M = -INFINITY;
#pragma unroll
        for (int kt = 0; kt < 16; ++kt)
            M = fmaxf(M, pmax[(size_t)(h * 16 + kt) * SEQ + qrow]);
        float S = 0.f;
#pragma unroll
        for (int kt = 0; kt < 16; ++kt) {
            size_t i = (size_t)(h * 16 + kt) * SEQ + qrow;
            S += psum[i] * __expf(pmax[i] - M);
        }
        sM[tid] = M;
        sI[tid] = 1.0f / S;
    }

    for (int it = 0; it < SEQ / 32; ++it) {
        const int s = it & 1;
        if (it + 1 < SEQ / 32) { issue_stage(it + 1, s ^ 1); CP_WAIT1(); }
        else                   { CP_WAIT0(); }
        __syncthreads();

        // convert S -> P in place, emit attn tile
        {
            char* pa = smem + s * PV_STAGE;
            char* pl = pa + PA_TILE;
#pragma unroll
            for (int j = 0; j < 2; ++j) {
                int idx = tid + j * 256;
                int r = idx >> 2, c = idx & 3;
                uint4 uh = *(uint4*)(pa + r * 80 + c * 16);
                uint4 ul = *(uint4*)(pl + r * 80 + c * 16);
                __nv_bfloat162* hb = (__nv_bfloat162*)&uh;
                __nv_bfloat162* lb = (__nv_bfloat162*)&ul;
                float m = sM[r], inv = sI[r];
                float p[8];
#pragma unroll
                for (int e = 0; e < 4; ++e) {
                    float sx = __bfloat162float(hb[e].x) + __bfloat162float(lb[e].x);
                    float sy = __bfloat162float(hb[e].y) + __bfloat162float(lb[e].y);
                    p[2 * e]     = __expf(sx - m) * inv;
                    p[2 * e + 1] = __expf(sy - m) * inv;
                }
                uint4 oh, ol;
                __nv_bfloat162* ohb = (__nv_bfloat162*)&oh;
                __nv_bfloat162* olb = (__nv_bfloat162*)&ol;
#pragma unroll
                for (int e = 0; e < 4; ++e) {
                    __nv_bfloat16 h0, h1, l0, l1;
                    split2(p[2 * e],     h0, l0);
                    split2(p[2 * e + 1], h1, l1);
                    ohb[e] = __nv_bfloat162(h0, h1);
                    olb[e] = __nv_bfloat162(l0, l1);
                }
                *(uint4*)(pa + r * 80 + c * 16) = oh;
                *(uint4*)(pl + r * 80 + c * 16) = ol;
                float* ga = attn + ((size_t)h * SEQ + bm + r) * SEQ + it * 32 + c * 8;
                *(float4*)ga       = make_float4(p[0], p[1], p[2], p[3]);
                *(float4*)(ga + 4) = make_float4(p[4], p[5], p[6], p[7]);
            }
        }
        __syncthreads();

        const uint32_t aHb = sb + s * PV_STAGE;
        const uint32_t aLb = aHb + PA_TILE;
        const uint32_t vHb = aHb + 2 * PA_TILE;
        const uint32_t vLb = vHb + PB_TILE;

#pragma unroll
        for (int ks = 0; ks < 2; ++ks) {
            uint32_t aoff = (uint32_t)((wm * 32 + (lane & 15)) * 80 + ks * 32 + (lane >> 4) * 16);
            uint32_t ah0[4], ah1[4], al0[4], al1[4];
            LDSM_X4(ah0[0], ah0[1], ah0[2], ah0[3], aHb + aoff);
            LDSM_X4(ah1[0], ah1[1], ah1[2], ah1[3], aHb + aoff + 16 * 80);
            LDSM_X4(al0[0], al0[1], al0[2], al0[3], aLb + aoff);
            LDSM_X4(al1[0], al1[1], al1[2], al1[3], aLb + aoff + 16 * 80);

            const int vrow = ks * 16 + ((lane >> 3) & 1) * 8 + (lane & 7);
            uint32_t bh[2][4], bl[2][4];
#pragma unroll
            for (int p = 0; p < 2; ++p) {
                int vcol = wn * 32 + p * 16 + ((lane >> 4) & 1) * 8;
                uint32_t voff = (uint32_t)(vrow * 144 + vcol * 2);
                LDSM_X4T(bh[p][0], bh[p][1], bh[p][2], bh[p][3], vHb + voff);
                LDSM_X4T(bl[p][0], bl[p][1], bl[p][2], bl[p][3], vLb + voff);
            }
#pragma unroll
            for (int mf = 0; mf < 2; ++mf) {
                const uint32_t* Ah_ = mf ? ah1 : ah0;
                const uint32_t* Al_ = mf ? al1 : al0;
#pragma unroll
                for (int p = 0; p < 2; ++p) {
                    MMA16816(acc[mf][2 * p],     Ah_, bh[p][0], bh[p][1]);
                    MMA16816(acc[mf][2 * p + 1], Ah_, bh[p][2], bh[p][3]);
                    MMA16816(acc[mf][2 * p],     Ah_, bl[p][0], bl[p][1]);
                    MMA16816(acc[mf][2 * p + 1], Ah_, bl[p][2], bl[p][3]);
                    MMA16816(acc[mf][2 * p],     Al_, bh[p][0], bh[p][1]);
                    MMA16816(acc[mf][2 * p + 1], Al_, bh[p][2], bh[p][3]);
                }
            }
        }
        __syncthreads();
    }

    const int l4 = lane >> 2;
    const int l2 = (lane & 3) * 2;
#pragma unroll
    for (int mf = 0; mf < 2; ++mf) {
        int q = bm + wm * 32 + mf * 16 + l4;
#pragma unroll
        for (int nf = 0; nf < 4; ++nf) {
            int col = h * DKH + wn * 32 + nf * 8 + l2;
            __nv_bfloat16 h0, h1, l0, l1;
            split2(acc[mf][nf][0], h0, l0);
            split2(acc[mf][nf][1], h1, l1);
            *(__nv_bfloat162*)&Ch[(size_t)q * DM + col] = __nv_bfloat162(h0, h1);
            *(__nv_bfloat162*)&Cl[(size_t)q * DM + col] = __nv_bfloat162(l0, l1);
            split2(acc[mf][nf][2], h0, l0);
            split2(acc[mf][nf][3], h1, l1);
            *(__nv_bfloat162*)&Ch[(size_t)(q + 8) * DM + col] = __nv_bfloat162(h0, h1);
            *(__nv_bfloat162*)&Cl[(size_t)(q + 8) * DM + col] = __nv_bfloat162(l0, l1);
        }
    }
}

// ===========================================================================
extern "C" void kernel_launch(void* const* d_in, const int* in_sizes, int n_in,
                              void* d_out, int out_size)
{
    const float* q    = (const float*)d_in[0];
    const float* k    = (const float*)d_in[1];
    const float* v    = (const float*)d_in[2];
    const int*   mask = (const int*)  d_in[3];
    const float* Wq   = (const float*)d_in[4];
    const float* bq   = (const float*)d_in[5];
    const float* Wk   = (const float*)d_in[6];
    const float* bk   = (const float*)d_in[7];
    const float* Wv   = (const float*)d_in[8];
    const float* bv   = (const float*)d_in[9];
    const float* Wo   = (const float*)d_in[10];
    const float* bo   = (const float*)d_in[11];

    float *Qp, *Kp, *Vp, *Ap, *Op, *pmaxp, *psump;
    cudaGetSymbolAddress((void**)&Qp, g_Q);
    cudaGetSymbolAddress((void**)&Kp, g_K);
    cudaGetSymbolAddress((void**)&Vp, g_V);
    cudaGetSymbolAddress((void**)&Ap, g_ATTN);
    cudaGetSymbolAddress((void**)&Op, g_OUT);
    cudaGetSymbolAddress((void**)&pmaxp, g_pmax);
    cudaGetSymbolAddress((void**)&psump, g_psum);

    __nv_bfloat16 *qh, *ql, *kh, *kl, *vh, *vl, *ch, *cl, *Shp, *Slp;
    __nv_bfloat16 *Wqh, *Wql, *Wkh, *Wkl, *Wvh, *Wvl, *Woh, *Wol;
    cudaGetSymbolAddress((void**)&qh, g_qh);   cudaGetSymbolAddress((void**)&ql, g_ql);
    cudaGetSymbolAddress((void**)&kh, g_kh);   cudaGetSymbolAddress((void**)&kl, g_kl);
    cudaGetSymbolAddress((void**)&vh, g_vh);   cudaGetSymbolAddress((void**)&vl, g_vl);
    cudaGetSymbolAddress((void**)&ch, g_ch);   cudaGetSymbolAddress((void**)&cl, g_cl);
    cudaGetSymbolAddress((void**)&Shp, g_Sh);  cudaGetSymbolAddress((void**)&Slp, g_Sl);
    cudaGetSymbolAddress((void**)&Wqh, g_Wqh); cudaGetSymbolAddress((void**)&Wql, g_Wql);
    cudaGetSymbolAddress((void**)&Wkh, g_Wkh); cudaGetSymbolAddress((void**)&Wkl, g_Wkl);
    cudaGetSymbolAddress((void**)&Wvh, g_Wvh); cudaGetSymbolAddress((void**)&Wvl, g_Wvl);
    cudaGetSymbolAddress((void**)&Woh, g_Woh); cudaGetSymbolAddress((void**)&Wol, g_Wol);

    // projected Q/K/V bf16 splits live inside the idle fp32 buffers
    __nv_bfloat16* pqh = (__nv_bfloat16*)Qp; __nv_bfloat16* pql = pqh + (size_t)SEQ * DM;
    __nv_bfloat16* pkh = (__nv_bfloat16*)Kp; __nv_bfloat16* pkl = pkh + (size_t)SEQ * DM;
    __nv_bfloat16* pvh = (__nv_bfloat16*)Vp; __nv_bfloat16* pvl = pvh + (size_t)SEQ * DM;

    const size_t OUT_ELEMS  = (size_t)SEQ * DM;
    const size_t ATTN_ELEMS = (size_t)NH * SEQ * SEQ;

    float* outp = (float*)d_out;
    float* attnp;
    if ((size_t)out_size >= OUT_ELEMS + ATTN_ELEMS) {
        attnp = outp + OUT_ELEMS;
    } else if ((size_t)out_size == ATTN_ELEMS) {
        attnp = (float*)d_out;
        outp  = Op;
    } else {
        attnp = Ap;
    }

    cudaFuncSetAttribute(gemm_mma,
                         cudaFuncAttributeMaxDynamicSharedMemorySize, GEMM_SMEM);
    cudaFuncSetAttribute(attn_sgemm,
                         cudaFuncAttributeMaxDynamicSharedMemorySize, SG_SMEM);
    cudaFuncSetAttribute(attn_pv2,
                         cudaFuncAttributeMaxDynamicSharedMemorySize, PV_SMEM);

    // 1) split inputs + weights
    {
        PrepBatch pb;
        pb.src[0] = q;  pb.hi[0] = qh;  pb.lo[0] = ql;  pb.n4[0] = SEQ * DM / 4;
        pb.src[1] = k;  pb.hi[1] = kh;  pb.lo[1] = kl;  pb.n4[1] = SEQ * DM / 4;
        pb.src[2] = v;  pb.hi[2] = vh;  pb.lo[2] = vl;  pb.n4[2] = SEQ * DM / 4;
        pb.src[3] = Wq; pb.hi[3] = Wqh; pb.lo[3] = Wql; pb.n4[3] = DM * DM / 4;
        pb.src[4] = Wk; pb.hi[4] = Wkh; pb.lo[4] = Wkl; pb.n4[4] = DM * DM / 4;
        pb.src[5] = Wv; pb.hi[5] = Wvh; pb.lo[5] = Wvl; pb.n4[5] = DM * DM / 4;
        pb.src[6] = Wo; pb.hi[6] = Woh; pb.lo[6] = Wol; pb.n4[6] = DM * DM / 4;
        pb.src[7] = q;  pb.hi[7] = qh;  pb.lo[7] = ql;  pb.n4[7] = 0;
        dim3 pg((SEQ * DM / 4 + 255) / 256, 1, 7);
        split_prep<<<pg, 256>>>(pb);
    }

    // 2) Q/K/V projections -> split bf16 outputs directly
    {
        GemmBatch gb;
        gb.g[0] = { qh, ql, Wqh, Wql, bq, nullptr, pqh, pql };
        gb.g[1] = { kh, kl, Wkh, Wkl, bk, nullptr, pkh, pkl };
        gb.g[2] = { vh, vl, Wvh, Wvl, bv, nullptr, pvh, pvl };
        gemm_mma<<<dim3(DM / 128, SEQ / 128, 3), 256, GEMM_SMEM>>>(gb);
    }

    // 3) scores GEMM -> split S + partial stats
    attn_sgemm<<<dim3(SEQ / 128, SEQ / 128, NH), 256, SG_SMEM>>>(
        pqh, pql, pkh, pkl, mask, Shp, Slp, pmaxp, psump);

    // 4) fused stats + softmax-emit + P@V -> split ctx
    attn_pv2<<<dim3(SEQ / 128, NH), 256, PV_SMEM>>>(
        Shp, Slp, pvh, pvl, pmaxp, psump, attnp, ch, cl);

    // 5) output projection (fp32 out)
    {
        GemmBatch gb;
        gb.g[0] = { ch, cl, Woh, Wol, bo, outp, nullptr, nullptr };
        gb.g[1] = gb.g[0];
        gb.g[2] = gb.g[0];
        gemm_mma<<<dim3(DM / 128, SEQ / 128, 1), 256, GEMM_SMEM>>>(gb);
    }
}